// round 2
// baseline (speedup 1.0000x reference)
#include <cuda_runtime.h>

#define NU 100000
#define NI 200000
#define NN 300000          // NU + NI
#define EMB 64
#define NE 1000000
#define BATCH 16384

// -------- scratch (device globals; no allocation allowed) ----------
__device__ float g_dinv[NN];                 // degree, then deg^-0.5
__device__ float g_w[4];                     // softmax(layer_weights)
__device__ float g_e0[(size_t)NN * EMB];
__device__ float g_e1[(size_t)NN * EMB];
__device__ float g_e2[(size_t)NN * EMB];
__device__ float g_e3[(size_t)NN * EMB];

// -------------------- small kernels --------------------------------
__global__ void zero_kernel(float* p, size_t n4) {
    size_t i = (size_t)blockIdx.x * blockDim.x + threadIdx.x;
    float4* p4 = (float4*)p;
    size_t stride = (size_t)gridDim.x * blockDim.x;
    for (; i < n4; i += stride) p4[i] = make_float4(0.f, 0.f, 0.f, 0.f);
}

__global__ void softmax_kernel(const float* __restrict__ lw) {
    // single thread: 4 values
    float m = lw[0];
    for (int i = 1; i < 4; i++) m = fmaxf(m, lw[i]);
    float s = 0.f, e[4];
    for (int i = 0; i < 4; i++) { e[i] = expf(lw[i] - m); s += e[i]; }
    for (int i = 0; i < 4; i++) g_w[i] = e[i] / s;
}

__global__ void count_deg_kernel(const int* __restrict__ eu,
                                 const int* __restrict__ ei) {
    int i = blockIdx.x * blockDim.x + threadIdx.x;
    if (i >= NE) return;
    atomicAdd(&g_dinv[eu[i]], 1.0f);
    atomicAdd(&g_dinv[NU + ei[i]], 1.0f);
}

__global__ void dinv_kernel() {
    int i = blockIdx.x * blockDim.x + threadIdx.x;
    if (i >= NN) return;
    float d = g_dinv[i];
    g_dinv[i] = (d > 0.f) ? rsqrtf(d) : 0.f;
}

__global__ void build_e0_kernel(const float* __restrict__ ue,
                                const float* __restrict__ ie) {
    // copy [user_emb ; item_emb] into g_e0, float4 granularity
    size_t n4 = (size_t)NN * EMB / 4;
    size_t i = (size_t)blockIdx.x * blockDim.x + threadIdx.x;
    size_t stride = (size_t)gridDim.x * blockDim.x;
    const float4* u4 = (const float4*)ue;
    const float4* i4 = (const float4*)ie;
    float4* e4 = (float4*)g_e0;
    size_t nu4 = (size_t)NU * EMB / 4;
    for (; i < n4; i += stride) {
        e4[i] = (i < nu4) ? u4[i] : i4[i - nu4];
    }
}

// one warp per interaction; each lane owns 2 dims (float2)
__global__ void prop_kernel(const int* __restrict__ eu,
                            const int* __restrict__ ei,
                            const float* __restrict__ prev,
                            float* __restrict__ next) {
    int gw = (blockIdx.x * blockDim.x + threadIdx.x) >> 5;
    if (gw >= NE) return;
    int lane = threadIdx.x & 31;
    int u = eu[gw];
    int v = NU + ei[gw];
    float w = g_dinv[u] * g_dinv[v];

    const float2* pu = (const float2*)(prev + (size_t)u * EMB);
    const float2* pv = (const float2*)(prev + (size_t)v * EMB);
    float2 a = pu[lane];   // u's row
    float2 b = pv[lane];   // v's row

    float2* nu = (float2*)(next + (size_t)u * EMB) + lane;
    float2* nv = (float2*)(next + (size_t)v * EMB) + lane;

    // next[v] += w * prev[u];  next[u] += w * prev[v];
    asm volatile("red.global.add.v2.f32 [%0], {%1, %2};"
                 :: "l"(nv), "f"(w * a.x), "f"(w * a.y) : "memory");
    asm volatile("red.global.add.v2.f32 [%0], {%1, %2};"
                 :: "l"(nu), "f"(w * b.x), "f"(w * b.y) : "memory");
}

// one warp per (user, item) pair; fold weighted layer sum into the dot
__global__ void score_kernel(const int* __restrict__ uids,
                             const int* __restrict__ iids,
                             float* __restrict__ out) {
    int gw = (blockIdx.x * blockDim.x + threadIdx.x) >> 5;
    if (gw >= BATCH) return;
    int lane = threadIdx.x & 31;
    int u = uids[gw];
    int v = NU + iids[gw];

    float w0 = g_w[0], w1 = g_w[1], w2 = g_w[2], w3 = g_w[3];

    const float2* u0 = (const float2*)(g_e0 + (size_t)u * EMB);
    const float2* u1 = (const float2*)(g_e1 + (size_t)u * EMB);
    const float2* u2 = (const float2*)(g_e2 + (size_t)u * EMB);
    const float2* u3 = (const float2*)(g_e3 + (size_t)u * EMB);
    const float2* v0 = (const float2*)(g_e0 + (size_t)v * EMB);
    const float2* v1 = (const float2*)(g_e1 + (size_t)v * EMB);
    const float2* v2 = (const float2*)(g_e2 + (size_t)v * EMB);
    const float2* v3 = (const float2*)(g_e3 + (size_t)v * EMB);

    float2 a0 = u0[lane], a1 = u1[lane], a2 = u2[lane], a3 = u3[lane];
    float2 b0 = v0[lane], b1 = v1[lane], b2 = v2[lane], b3 = v3[lane];

    float ufx = w0 * a0.x + w1 * a1.x + w2 * a2.x + w3 * a3.x;
    float ufy = w0 * a0.y + w1 * a1.y + w2 * a2.y + w3 * a3.y;
    float vfx = w0 * b0.x + w1 * b1.x + w2 * b2.x + w3 * b3.x;
    float vfy = w0 * b0.y + w1 * b1.y + w2 * b2.y + w3 * b3.y;

    float acc = ufx * vfx + ufy * vfy;
    #pragma unroll
    for (int off = 16; off > 0; off >>= 1)
        acc += __shfl_down_sync(0xffffffffu, acc, off);
    if (lane == 0) out[gw] = acc;
}

// ------------------------- launcher --------------------------------
extern "C" void kernel_launch(void* const* d_in, const int* in_sizes, int n_in,
                              void* d_out, int out_size) {
    const float* user_emb = (const float*)d_in[0];
    const float* item_emb = (const float*)d_in[1];
    const float* layer_w  = (const float*)d_in[2];
    const int*   eu       = (const int*)d_in[3];
    const int*   ei       = (const int*)d_in[4];
    const int*   uids     = (const int*)d_in[5];
    const int*   iids     = (const int*)d_in[6];
    float*       out      = (float*)d_out;
    (void)in_sizes; (void)n_in; (void)out_size;

    float *e0, *e1, *e2, *e3, *dinv;
    cudaGetSymbolAddress((void**)&e0, g_e0);
    cudaGetSymbolAddress((void**)&e1, g_e1);
    cudaGetSymbolAddress((void**)&e2, g_e2);
    cudaGetSymbolAddress((void**)&e3, g_e3);
    cudaGetSymbolAddress((void**)&dinv, g_dinv);

    const size_t embN4 = (size_t)NN * EMB / 4;

    softmax_kernel<<<1, 1>>>(layer_w);

    // degrees
    zero_kernel<<<(NN / 4 + 255) / 256, 256>>>(dinv, NN / 4);
    count_deg_kernel<<<(NE + 255) / 256, 256>>>(eu, ei);
    dinv_kernel<<<(NN + 255) / 256, 256>>>();

    // e0 = [user_emb ; item_emb]
    build_e0_kernel<<<2048, 256>>>(user_emb, item_emb);

    const int PROP_BLOCKS = (NE * 32 + 255) / 256;

    // layer 1
    zero_kernel<<<2048, 256>>>(e1, embN4);
    prop_kernel<<<PROP_BLOCKS, 256>>>(eu, ei, e0, e1);
    // layer 2
    zero_kernel<<<2048, 256>>>(e2, embN4);
    prop_kernel<<<PROP_BLOCKS, 256>>>(eu, ei, e1, e2);
    // layer 3
    zero_kernel<<<2048, 256>>>(e3, embN4);
    prop_kernel<<<PROP_BLOCKS, 256>>>(eu, ei, e2, e3);

    // scores
    score_kernel<<<(BATCH * 32 + 255) / 256, 256>>>(uids, iids, out);
}

// round 5
// speedup vs baseline: 1.3611x; 1.3611x over previous
#include <cuda_runtime.h>

#define NU 100000
#define NI 200000
#define NN 300000          // NU + NI
#define EMB 64
#define NE 1000000
#define BATCH 16384

#define SCAN_BS 1024
#define NSB ((NN + SCAN_BS - 1) / SCAN_BS)   // 293

// -------- scratch (device globals; no allocation allowed) ----------
__device__ int    g_cnt[NN];        // degree counts
__device__ int    g_scan[NN];       // per-block inclusive scan
__device__ int    g_bsum[NSB];
__device__ int    g_boff[NSB];
__device__ int    g_off[NN + 1];    // CSR row offsets
__device__ int    g_cursor[NN];     // fill cursors
__device__ float  g_dinv[NN];       // deg^-0.5
__device__ float  g_w[4];           // softmax(layer_weights)
__device__ float2 g_adj[2 * NE];    // {dst (int bits), edge weight}
__device__ float  g_e1[(size_t)NN * EMB];
__device__ float  g_e2[(size_t)NN * EMB];
__device__ float  g_e3[(size_t)NN * EMB];

// -------------------- small kernels --------------------------------
__global__ void zero_cnt_kernel() {
    int i = blockIdx.x * blockDim.x + threadIdx.x;
    if (i < NN) g_cnt[i] = 0;
}

__global__ void softmax_kernel(const float* __restrict__ lw) {
    float m = lw[0];
    for (int i = 1; i < 4; i++) m = fmaxf(m, lw[i]);
    float s = 0.f, e[4];
    for (int i = 0; i < 4; i++) { e[i] = expf(lw[i] - m); s += e[i]; }
    for (int i = 0; i < 4; i++) g_w[i] = e[i] / s;
}

__global__ void hist_kernel(const int* __restrict__ eu,
                            const int* __restrict__ ei) {
    int i = blockIdx.x * blockDim.x + threadIdx.x;
    if (i >= NE) return;
    atomicAdd(&g_cnt[eu[i]], 1);
    atomicAdd(&g_cnt[NU + ei[i]], 1);
}

// per-block inclusive scan of counts
__global__ void scanA_kernel() {
    __shared__ int sh[SCAN_BS];
    int tid = threadIdx.x;
    int i = blockIdx.x * SCAN_BS + tid;
    int v = (i < NN) ? g_cnt[i] : 0;
    sh[tid] = v;
    __syncthreads();
    #pragma unroll
    for (int off = 1; off < SCAN_BS; off <<= 1) {
        int t = (tid >= off) ? sh[tid - off] : 0;
        __syncthreads();
        sh[tid] += t;
        __syncthreads();
    }
    if (i < NN) g_scan[i] = sh[tid];
    if (tid == SCAN_BS - 1) g_bsum[blockIdx.x] = sh[tid];
}

// exclusive scan over block sums (293 elements — sequential is fine)
__global__ void scanB_kernel() {
    if (threadIdx.x == 0) {
        int run = 0;
        for (int b = 0; b < NSB; b++) { g_boff[b] = run; run += g_bsum[b]; }
    }
}

// finalize: exclusive offsets, cursors, dinv
__global__ void scanC_kernel() {
    int i = blockIdx.x * SCAN_BS + threadIdx.x;
    if (i >= NN) return;
    int c = g_cnt[i];
    int excl = g_scan[i] - c + g_boff[blockIdx.x];
    g_off[i] = excl;
    g_cursor[i] = excl;
    g_dinv[i] = (c > 0) ? rsqrtf((float)c) : 0.f;
    if (i == NN - 1) g_off[NN] = excl + c;
}

__global__ void fill_kernel(const int* __restrict__ eu,
                            const int* __restrict__ ei) {
    int i = blockIdx.x * blockDim.x + threadIdx.x;
    if (i >= NE) return;
    int u = eu[i];
    int v = NU + ei[i];
    float w = g_dinv[u] * g_dinv[v];
    int p = atomicAdd(&g_cursor[u], 1);
    g_adj[p] = make_float2(__int_as_float(v), w);
    int q = atomicAdd(&g_cursor[v], 1);
    g_adj[q] = make_float2(__int_as_float(u), w);
}

// gather propagation: one warp per node, lane owns 2 dims
template <bool FIRST>
__global__ void prop_kernel(const float* __restrict__ prev,
                            const float* __restrict__ ue,
                            const float* __restrict__ ie,
                            float* __restrict__ next) {
    int node = (blockIdx.x * blockDim.x + threadIdx.x) >> 5;
    if (node >= NN) return;
    int lane = threadIdx.x & 31;
    int start = g_off[node];
    int end   = g_off[node + 1];
    float2 acc = make_float2(0.f, 0.f);

    for (int base = start; base < end; base += 32) {
        int n = min(32, end - base);
        float2 e = make_float2(0.f, 0.f);
        if (lane < n) e = g_adj[base + lane];
        int   dst_r = __float_as_int(e.x);
        float w_r   = e.y;
        for (int j = 0; j < n; j++) {
            int   v = __shfl_sync(0xffffffffu, dst_r, j);
            float w = __shfl_sync(0xffffffffu, w_r, j);
            const float2* row;
            if (FIRST) {
                row = (v < NU) ? (const float2*)(ue + (size_t)v * EMB)
                               : (const float2*)(ie + (size_t)(v - NU) * EMB);
            } else {
                row = (const float2*)(prev + (size_t)v * EMB);
            }
            float2 p = row[lane];
            acc.x += w * p.x;
            acc.y += w * p.y;
        }
    }
    ((float2*)(next + (size_t)node * EMB))[lane] = acc;
}

// one warp per (user, item) pair; weighted layer sum folded into the dot
__global__ void score_kernel(const int* __restrict__ uids,
                             const int* __restrict__ iids,
                             const float* __restrict__ ue,
                             const float* __restrict__ ie,
                             float* __restrict__ out) {
    int gw = (blockIdx.x * blockDim.x + threadIdx.x) >> 5;
    if (gw >= BATCH) return;
    int lane = threadIdx.x & 31;
    int u = uids[gw];
    int iv = iids[gw];
    int v = NU + iv;

    float w0 = g_w[0], w1 = g_w[1], w2 = g_w[2], w3 = g_w[3];

    float2 a0 = ((const float2*)(ue + (size_t)u * EMB))[lane];
    float2 a1 = ((const float2*)(g_e1 + (size_t)u * EMB))[lane];
    float2 a2 = ((const float2*)(g_e2 + (size_t)u * EMB))[lane];
    float2 a3 = ((const float2*)(g_e3 + (size_t)u * EMB))[lane];
    float2 b0 = ((const float2*)(ie + (size_t)iv * EMB))[lane];
    float2 b1 = ((const float2*)(g_e1 + (size_t)v * EMB))[lane];
    float2 b2 = ((const float2*)(g_e2 + (size_t)v * EMB))[lane];
    float2 b3 = ((const float2*)(g_e3 + (size_t)v * EMB))[lane];

    float ufx = w0 * a0.x + w1 * a1.x + w2 * a2.x + w3 * a3.x;
    float ufy = w0 * a0.y + w1 * a1.y + w2 * a2.y + w3 * a3.y;
    float vfx = w0 * b0.x + w1 * b1.x + w2 * b2.x + w3 * b3.x;
    float vfy = w0 * b0.y + w1 * b1.y + w2 * b2.y + w3 * b3.y;

    float acc = ufx * vfx + ufy * vfy;
    #pragma unroll
    for (int off = 16; off > 0; off >>= 1)
        acc += __shfl_down_sync(0xffffffffu, acc, off);
    if (lane == 0) out[gw] = acc;
}

// ------------------------- launcher --------------------------------
extern "C" void kernel_launch(void* const* d_in, const int* in_sizes, int n_in,
                              void* d_out, int out_size) {
    const float* user_emb = (const float*)d_in[0];
    const float* item_emb = (const float*)d_in[1];
    const float* layer_w  = (const float*)d_in[2];
    const int*   eu       = (const int*)d_in[3];
    const int*   ei       = (const int*)d_in[4];
    const int*   uids     = (const int*)d_in[5];
    const int*   iids     = (const int*)d_in[6];
    float*       out      = (float*)d_out;
    (void)in_sizes; (void)n_in; (void)out_size;

    float *e1, *e2, *e3;
    cudaGetSymbolAddress((void**)&e1, g_e1);
    cudaGetSymbolAddress((void**)&e2, g_e2);
    cudaGetSymbolAddress((void**)&e3, g_e3);

    softmax_kernel<<<1, 1>>>(layer_w);

    // ---- CSR build ----
    zero_cnt_kernel<<<(NN + 255) / 256, 256>>>();
    hist_kernel<<<(NE + 255) / 256, 256>>>(eu, ei);
    scanA_kernel<<<NSB, SCAN_BS>>>();
    scanB_kernel<<<1, 32>>>();
    scanC_kernel<<<NSB, SCAN_BS>>>();
    fill_kernel<<<(NE + 255) / 256, 256>>>(eu, ei);

    // ---- 3 gather layers ----
    const int PROP_BLOCKS = (NN * 32 + 255) / 256;
    prop_kernel<true ><<<PROP_BLOCKS, 256>>>(nullptr, user_emb, item_emb, e1);
    prop_kernel<false><<<PROP_BLOCKS, 256>>>(e1, nullptr, nullptr, e2);
    prop_kernel<false><<<PROP_BLOCKS, 256>>>(e2, nullptr, nullptr, e3);

    // ---- scores ----
    score_kernel<<<(BATCH * 32 + 255) / 256, 256>>>(uids, iids, user_emb, item_emb, out);
}

// round 6
// speedup vs baseline: 1.8240x; 1.3401x over previous
#include <cuda_runtime.h>

#define NU 100000
#define NI 200000
#define NN 300000          // NU + NI
#define EMB 64
#define NE 1000000
#define BATCH 16384

#define SCAN_BS 1024
#define NSB ((NN + SCAN_BS - 1) / SCAN_BS)   // 293

// -------- scratch (device globals; no allocation allowed) ----------
__device__ int    g_cnt[NN];        // degree counts
__device__ int    g_scan[NN];       // per-block inclusive scan
__device__ int    g_bsum[NSB];
__device__ int    g_boff[NSB];
__device__ int    g_off[NN + 1];    // CSR row offsets
__device__ int    g_cursor[NN];     // fill cursors
__device__ float  g_dinv[NN];       // deg^-0.5
__device__ float  g_w[4];           // softmax(layer_weights)
__device__ float2 g_adj[2 * NE];    // {dst (int bits), edge weight}
__device__ float  g_e1[(size_t)NN * EMB];
__device__ float  g_e2[(size_t)NN * EMB];
__device__ float  g_e3[(size_t)NN * EMB];

// -------------------- small kernels --------------------------------
__global__ void zero_cnt_kernel() {
    int i = blockIdx.x * blockDim.x + threadIdx.x;
    if (i < NN) g_cnt[i] = 0;
}

__global__ void softmax_kernel(const float* __restrict__ lw) {
    float m = lw[0];
    for (int i = 1; i < 4; i++) m = fmaxf(m, lw[i]);
    float s = 0.f, e[4];
    for (int i = 0; i < 4; i++) { e[i] = expf(lw[i] - m); s += e[i]; }
    for (int i = 0; i < 4; i++) g_w[i] = e[i] / s;
}

__global__ void hist_kernel(const int* __restrict__ eu,
                            const int* __restrict__ ei) {
    int i = blockIdx.x * blockDim.x + threadIdx.x;
    if (i >= NE) return;
    atomicAdd(&g_cnt[eu[i]], 1);
    atomicAdd(&g_cnt[NU + ei[i]], 1);
}

// per-block inclusive scan of counts
__global__ void scanA_kernel() {
    __shared__ int sh[SCAN_BS];
    int tid = threadIdx.x;
    int i = blockIdx.x * SCAN_BS + tid;
    int v = (i < NN) ? g_cnt[i] : 0;
    sh[tid] = v;
    __syncthreads();
    #pragma unroll
    for (int off = 1; off < SCAN_BS; off <<= 1) {
        int t = (tid >= off) ? sh[tid - off] : 0;
        __syncthreads();
        sh[tid] += t;
        __syncthreads();
    }
    if (i < NN) g_scan[i] = sh[tid];
    if (tid == SCAN_BS - 1) g_bsum[blockIdx.x] = sh[tid];
}

// exclusive scan over the 293 block sums — one block, shared-mem scan
__global__ void scanB_kernel() {
    __shared__ int sh[512];
    int tid = threadIdx.x;
    int v = (tid < NSB) ? g_bsum[tid] : 0;
    sh[tid] = v;
    __syncthreads();
    #pragma unroll
    for (int off = 1; off < 512; off <<= 1) {
        int t = (tid >= off) ? sh[tid - off] : 0;
        __syncthreads();
        sh[tid] += t;
        __syncthreads();
    }
    if (tid < NSB) g_boff[tid] = sh[tid] - v;   // exclusive
}

// finalize: exclusive offsets, cursors, dinv
__global__ void scanC_kernel() {
    int i = blockIdx.x * SCAN_BS + threadIdx.x;
    if (i >= NN) return;
    int c = g_cnt[i];
    int excl = g_scan[i] - c + g_boff[blockIdx.x];
    g_off[i] = excl;
    g_cursor[i] = excl;
    g_dinv[i] = (c > 0) ? rsqrtf((float)c) : 0.f;
    if (i == NN - 1) g_off[NN] = excl + c;
}

__global__ void fill_kernel(const int* __restrict__ eu,
                            const int* __restrict__ ei) {
    int i = blockIdx.x * blockDim.x + threadIdx.x;
    if (i >= NE) return;
    int u = eu[i];
    int v = NU + ei[i];
    float w = g_dinv[u] * g_dinv[v];
    int p = atomicAdd(&g_cursor[u], 1);
    g_adj[p] = make_float2(__int_as_float(v), w);
    int q = atomicAdd(&g_cursor[v], 1);
    g_adj[q] = make_float2(__int_as_float(u), w);
}

// gather propagation: 2 nodes per warp, 16 lanes per node, float4 per lane.
// Each shuffle step issues 2 independent 256B row gathers (one per half-warp).
template <bool FIRST>
__global__ void prop_kernel(const float* __restrict__ prev,
                            const float* __restrict__ ue,
                            const float* __restrict__ ie,
                            float* __restrict__ next) {
    int warpId = (blockIdx.x * blockDim.x + threadIdx.x) >> 5;
    int lane = threadIdx.x & 31;
    int half = lane >> 4;            // 0 or 1
    int sub  = lane & 15;            // lane within half-warp
    int node = warpId * 2 + half;
    if (node >= NN) return;          // whole half-warp exits together

    unsigned mask = 0xFFFFu << (half * 16);

    int start = g_off[node];
    int end   = g_off[node + 1];
    float4 acc = make_float4(0.f, 0.f, 0.f, 0.f);

    for (int base = start; base < end; base += 16) {
        int n = min(16, end - base);
        float2 e = make_float2(0.f, 0.f);
        if (sub < n) e = g_adj[base + sub];
        int   dst_r = __float_as_int(e.x);
        float w_r   = e.y;
        for (int j = 0; j < n; j++) {
            int   v = __shfl_sync(mask, dst_r, j, 16);
            float w = __shfl_sync(mask, w_r, j, 16);
            const float4* row;
            if (FIRST) {
                row = (v < NU) ? (const float4*)(ue + (size_t)v * EMB)
                               : (const float4*)(ie + (size_t)(v - NU) * EMB);
            } else {
                row = (const float4*)(prev + (size_t)v * EMB);
            }
            float4 p = row[sub];
            acc.x += w * p.x;
            acc.y += w * p.y;
            acc.z += w * p.z;
            acc.w += w * p.w;
        }
    }
    ((float4*)(next + (size_t)node * EMB))[sub] = acc;
}

// one warp per (user, item) pair; weighted layer sum folded into the dot
__global__ void score_kernel(const int* __restrict__ uids,
                             const int* __restrict__ iids,
                             const float* __restrict__ ue,
                             const float* __restrict__ ie,
                             float* __restrict__ out) {
    int gw = (blockIdx.x * blockDim.x + threadIdx.x) >> 5;
    if (gw >= BATCH) return;
    int lane = threadIdx.x & 31;
    int u = uids[gw];
    int iv = iids[gw];
    int v = NU + iv;

    float w0 = g_w[0], w1 = g_w[1], w2 = g_w[2], w3 = g_w[3];

    float2 a0 = ((const float2*)(ue + (size_t)u * EMB))[lane];
    float2 a1 = ((const float2*)(g_e1 + (size_t)u * EMB))[lane];
    float2 a2 = ((const float2*)(g_e2 + (size_t)u * EMB))[lane];
    float2 a3 = ((const float2*)(g_e3 + (size_t)u * EMB))[lane];
    float2 b0 = ((const float2*)(ie + (size_t)iv * EMB))[lane];
    float2 b1 = ((const float2*)(g_e1 + (size_t)v * EMB))[lane];
    float2 b2 = ((const float2*)(g_e2 + (size_t)v * EMB))[lane];
    float2 b3 = ((const float2*)(g_e3 + (size_t)v * EMB))[lane];

    float ufx = w0 * a0.x + w1 * a1.x + w2 * a2.x + w3 * a3.x;
    float ufy = w0 * a0.y + w1 * a1.y + w2 * a2.y + w3 * a3.y;
    float vfx = w0 * b0.x + w1 * b1.x + w2 * b2.x + w3 * b3.x;
    float vfy = w0 * b0.y + w1 * b1.y + w2 * b2.y + w3 * b3.y;

    float acc = ufx * vfx + ufy * vfy;
    #pragma unroll
    for (int off = 16; off > 0; off >>= 1)
        acc += __shfl_down_sync(0xffffffffu, acc, off);
    if (lane == 0) out[gw] = acc;
}

// ------------------------- launcher --------------------------------
extern "C" void kernel_launch(void* const* d_in, const int* in_sizes, int n_in,
                              void* d_out, int out_size) {
    const float* user_emb = (const float*)d_in[0];
    const float* item_emb = (const float*)d_in[1];
    const float* layer_w  = (const float*)d_in[2];
    const int*   eu       = (const int*)d_in[3];
    const int*   ei       = (const int*)d_in[4];
    const int*   uids     = (const int*)d_in[5];
    const int*   iids     = (const int*)d_in[6];
    float*       out      = (float*)d_out;
    (void)in_sizes; (void)n_in; (void)out_size;

    float *e1, *e2, *e3;
    cudaGetSymbolAddress((void**)&e1, g_e1);
    cudaGetSymbolAddress((void**)&e2, g_e2);
    cudaGetSymbolAddress((void**)&e3, g_e3);

    softmax_kernel<<<1, 1>>>(layer_w);

    // ---- CSR build ----
    zero_cnt_kernel<<<(NN + 255) / 256, 256>>>();
    hist_kernel<<<(NE + 255) / 256, 256>>>(eu, ei);
    scanA_kernel<<<NSB, SCAN_BS>>>();
    scanB_kernel<<<1, 512>>>();
    scanC_kernel<<<NSB, SCAN_BS>>>();
    fill_kernel<<<(NE + 255) / 256, 256>>>(eu, ei);

    // ---- 3 gather layers (2 nodes per warp, 16 threads each) ----
    const int PROP_WARPS  = (NN + 1) / 2;
    const int PROP_BLOCKS = (PROP_WARPS * 32 + 255) / 256;
    prop_kernel<true ><<<PROP_BLOCKS, 256>>>(nullptr, user_emb, item_emb, e1);
    prop_kernel<false><<<PROP_BLOCKS, 256>>>(e1, nullptr, nullptr, e2);
    prop_kernel<false><<<PROP_BLOCKS, 256>>>(e2, nullptr, nullptr, e3);

    // ---- scores ----
    score_kernel<<<(BATCH * 32 + 255) / 256, 256>>>(uids, iids, user_emb, item_emb, out);
}

// round 8
// speedup vs baseline: 2.2142x; 1.2139x over previous
#include <cuda_runtime.h>

#define NU 100000
#define NI 200000
#define NN 300000          // NU + NI
#define EMB 64
#define NE 1000000
#define BATCH 16384
#define MAXL3 (2 * BATCH)  // max distinct batch nodes

#define SCAN_BS 1024
#define NSB ((NN + SCAN_BS - 1) / SCAN_BS)   // 293

// -------- scratch (device globals; no allocation allowed) ----------
__device__ int    g_cnt[NN];        // degree counts
__device__ int    g_scan[NN];       // per-block inclusive scan
__device__ int    g_bsum[NSB];
__device__ int    g_boff[NSB];
__device__ int    g_off[NN + 1];    // CSR row offsets
__device__ int    g_cursor[NN];     // fill cursors
__device__ float  g_dinv[NN];       // deg^-0.5
__device__ float  g_w[4];           // softmax(layer_weights)
__device__ float2 g_adj[2 * NE];    // {dst (int bits), edge weight}
__device__ float  g_e1[(size_t)NN * EMB];
__device__ float  g_e2[(size_t)NN * EMB];
__device__ float  g_e3[(size_t)NN * EMB];
__device__ int    g_flag2[NN];
__device__ int    g_flag3[NN];
__device__ int    g_list2[NN];
__device__ int    g_list3[MAXL3];
__device__ int    g_n2;
__device__ int    g_n3;

// -------------------- small kernels --------------------------------
__global__ void zero_misc_kernel() {
    int i = blockIdx.x * blockDim.x + threadIdx.x;
    if (i < NN) { g_cnt[i] = 0; g_flag2[i] = 0; g_flag3[i] = 0; }
    if (i == 0) { g_n2 = 0; g_n3 = 0; }
}

__global__ void softmax_kernel(const float* __restrict__ lw) {
    float m = lw[0];
    for (int i = 1; i < 4; i++) m = fmaxf(m, lw[i]);
    float s = 0.f, e[4];
    for (int i = 0; i < 4; i++) { e[i] = expf(lw[i] - m); s += e[i]; }
    for (int i = 0; i < 4; i++) g_w[i] = e[i] / s;
}

__global__ void hist_kernel(const int* __restrict__ eu,
                            const int* __restrict__ ei) {
    int i = blockIdx.x * blockDim.x + threadIdx.x;
    if (i >= NE) return;
    atomicAdd(&g_cnt[eu[i]], 1);
    atomicAdd(&g_cnt[NU + ei[i]], 1);
}

__global__ void scanA_kernel() {
    __shared__ int sh[SCAN_BS];
    int tid = threadIdx.x;
    int i = blockIdx.x * SCAN_BS + tid;
    int v = (i < NN) ? g_cnt[i] : 0;
    sh[tid] = v;
    __syncthreads();
    #pragma unroll
    for (int off = 1; off < SCAN_BS; off <<= 1) {
        int t = (tid >= off) ? sh[tid - off] : 0;
        __syncthreads();
        sh[tid] += t;
        __syncthreads();
    }
    if (i < NN) g_scan[i] = sh[tid];
    if (tid == SCAN_BS - 1) g_bsum[blockIdx.x] = sh[tid];
}

__global__ void scanB_kernel() {
    __shared__ int sh[512];
    int tid = threadIdx.x;
    int v = (tid < NSB) ? g_bsum[tid] : 0;
    sh[tid] = v;
    __syncthreads();
    #pragma unroll
    for (int off = 1; off < 512; off <<= 1) {
        int t = (tid >= off) ? sh[tid - off] : 0;
        __syncthreads();
        sh[tid] += t;
        __syncthreads();
    }
    if (tid < NSB) g_boff[tid] = sh[tid] - v;   // exclusive
}

__global__ void scanC_kernel() {
    int i = blockIdx.x * SCAN_BS + threadIdx.x;
    if (i >= NN) return;
    int c = g_cnt[i];
    int excl = g_scan[i] - c + g_boff[blockIdx.x];
    g_off[i] = excl;
    g_cursor[i] = excl;
    g_dinv[i] = (c > 0) ? rsqrtf((float)c) : 0.f;
    if (i == NN - 1) g_off[NN] = excl + c;
}

__global__ void fill_kernel(const int* __restrict__ eu,
                            const int* __restrict__ ei) {
    int i = blockIdx.x * blockDim.x + threadIdx.x;
    if (i >= NE) return;
    int u = eu[i];
    int v = NU + ei[i];
    float w = g_dinv[u] * g_dinv[v];
    int p = atomicAdd(&g_cursor[u], 1);
    g_adj[p] = make_float2(__int_as_float(v), w);
    int q = atomicAdd(&g_cursor[v], 1);
    g_adj[q] = make_float2(__int_as_float(u), w);
}

// ------------- frontier marking / compaction -----------------------
__global__ void mark3_kernel(const int* __restrict__ uids,
                             const int* __restrict__ iids) {
    int i = blockIdx.x * blockDim.x + threadIdx.x;
    if (i >= BATCH) return;
    int u = uids[i];
    int v = NU + iids[i];
    g_flag3[u] = 1; g_flag3[v] = 1;
    g_flag2[u] = 1; g_flag2[v] = 1;
}

__global__ void compact3_kernel() {
    int i = blockIdx.x * blockDim.x + threadIdx.x;
    if (i >= NN) return;
    if (g_flag3[i]) { int p = atomicAdd(&g_n3, 1); g_list3[p] = i; }
}

// neighbors of needed3 nodes need e2 (one warp per list3 entry)
__global__ void mark2_kernel() {
    int idx = (blockIdx.x * blockDim.x + threadIdx.x) >> 5;
    if (idx >= g_n3) return;
    int lane = threadIdx.x & 31;
    int node = g_list3[idx];
    int start = g_off[node], end = g_off[node + 1];
    for (int p = start + lane; p < end; p += 32) {
        int v = __float_as_int(g_adj[p].x);
        g_flag2[v] = 1;
    }
}

__global__ void compact2_kernel() {
    int i = blockIdx.x * blockDim.x + threadIdx.x;
    if (i >= NN) return;
    if (g_flag2[i]) { int p = atomicAdd(&g_n2, 1); g_list2[p] = i; }
}

// ---------------- gather propagation core --------------------------
// node handled by a 16-lane half-warp; lane owns float4 (4 dims).
// inner loop unrolled by 4 -> 4 independent LDG.128 in flight.
template <bool FIRST>
__device__ __forceinline__ void gather_node(int node, int sub, unsigned mask,
                                            const float* __restrict__ prev,
                                            const float* __restrict__ ue,
                                            const float* __restrict__ ie,
                                            float* __restrict__ next) {
    int start = g_off[node];
    int end   = g_off[node + 1];
    float4 acc = make_float4(0.f, 0.f, 0.f, 0.f);

    for (int base = start; base < end; base += 16) {
        int n = min(16, end - base);
        float2 e = make_float2(0.f, 0.f);
        if (sub < n) e = g_adj[base + sub];
        int   dr = __float_as_int(e.x);
        float wr = e.y;
        int j = 0;
        for (; j + 4 <= n; j += 4) {
            int   v0 = __shfl_sync(mask, dr, j + 0, 16);
            int   v1 = __shfl_sync(mask, dr, j + 1, 16);
            int   v2 = __shfl_sync(mask, dr, j + 2, 16);
            int   v3 = __shfl_sync(mask, dr, j + 3, 16);
            float w0 = __shfl_sync(mask, wr, j + 0, 16);
            float w1 = __shfl_sync(mask, wr, j + 1, 16);
            float w2 = __shfl_sync(mask, wr, j + 2, 16);
            float w3 = __shfl_sync(mask, wr, j + 3, 16);
            const float4 *r0, *r1, *r2, *r3;
            if (FIRST) {
                r0 = (v0 < NU) ? (const float4*)(ue + (size_t)v0 * EMB)
                               : (const float4*)(ie + (size_t)(v0 - NU) * EMB);
                r1 = (v1 < NU) ? (const float4*)(ue + (size_t)v1 * EMB)
                               : (const float4*)(ie + (size_t)(v1 - NU) * EMB);
                r2 = (v2 < NU) ? (const float4*)(ue + (size_t)v2 * EMB)
                               : (const float4*)(ie + (size_t)(v2 - NU) * EMB);
                r3 = (v3 < NU) ? (const float4*)(ue + (size_t)v3 * EMB)
                               : (const float4*)(ie + (size_t)(v3 - NU) * EMB);
            } else {
                r0 = (const float4*)(prev + (size_t)v0 * EMB);
                r1 = (const float4*)(prev + (size_t)v1 * EMB);
                r2 = (const float4*)(prev + (size_t)v2 * EMB);
                r3 = (const float4*)(prev + (size_t)v3 * EMB);
            }
            float4 p0 = r0[sub], p1 = r1[sub], p2 = r2[sub], p3 = r3[sub];
            acc.x += w0 * p0.x; acc.y += w0 * p0.y; acc.z += w0 * p0.z; acc.w += w0 * p0.w;
            acc.x += w1 * p1.x; acc.y += w1 * p1.y; acc.z += w1 * p1.z; acc.w += w1 * p1.w;
            acc.x += w2 * p2.x; acc.y += w2 * p2.y; acc.z += w2 * p2.z; acc.w += w2 * p2.w;
            acc.x += w3 * p3.x; acc.y += w3 * p3.y; acc.z += w3 * p3.z; acc.w += w3 * p3.w;
        }
        for (; j < n; j++) {
            int   v = __shfl_sync(mask, dr, j, 16);
            float w = __shfl_sync(mask, wr, j, 16);
            const float4* r;
            if (FIRST) {
                r = (v < NU) ? (const float4*)(ue + (size_t)v * EMB)
                             : (const float4*)(ie + (size_t)(v - NU) * EMB);
            } else {
                r = (const float4*)(prev + (size_t)v * EMB);
            }
            float4 p = r[sub];
            acc.x += w * p.x; acc.y += w * p.y; acc.z += w * p.z; acc.w += w * p.w;
        }
    }
    ((float4*)(next + (size_t)node * EMB))[sub] = acc;
}

// full propagation over all NN nodes (layer 1)
__global__ void prop_full_kernel(const float* __restrict__ ue,
                                 const float* __restrict__ ie,
                                 float* __restrict__ next) {
    int warpId = (blockIdx.x * blockDim.x + threadIdx.x) >> 5;
    int lane = threadIdx.x & 31;
    int half = lane >> 4;
    int sub  = lane & 15;
    int node = warpId * 2 + half;
    if (node >= NN) return;
    unsigned mask = 0xFFFFu << (half * 16);
    gather_node<true>(node, sub, mask, nullptr, ue, ie, next);
}

// list-driven propagation (layers 2, 3)
__global__ void prop_list_kernel(const float* __restrict__ prev,
                                 float* __restrict__ next,
                                 const int* __restrict__ list,
                                 const int* __restrict__ count) {
    int warpId = (blockIdx.x * blockDim.x + threadIdx.x) >> 5;
    int lane = threadIdx.x & 31;
    int cnt = __shfl_sync(0xffffffffu, (lane == 0) ? *count : 0, 0);
    int half = lane >> 4;
    int sub  = lane & 15;
    int idx = warpId * 2 + half;
    if (idx >= cnt) return;
    int node = list[idx];
    unsigned mask = 0xFFFFu << (half * 16);
    gather_node<false>(node, sub, mask, prev, nullptr, nullptr, next);
}

// one warp per (user, item) pair; weighted layer sum folded into the dot
__global__ void score_kernel(const int* __restrict__ uids,
                             const int* __restrict__ iids,
                             const float* __restrict__ ue,
                             const float* __restrict__ ie,
                             float* __restrict__ out) {
    int gw = (blockIdx.x * blockDim.x + threadIdx.x) >> 5;
    if (gw >= BATCH) return;
    int lane = threadIdx.x & 31;
    int u = uids[gw];
    int iv = iids[gw];
    int v = NU + iv;

    float w0 = g_w[0], w1 = g_w[1], w2 = g_w[2], w3 = g_w[3];

    float2 a0 = ((const float2*)(ue + (size_t)u * EMB))[lane];
    float2 a1 = ((const float2*)(g_e1 + (size_t)u * EMB))[lane];
    float2 a2 = ((const float2*)(g_e2 + (size_t)u * EMB))[lane];
    float2 a3 = ((const float2*)(g_e3 + (size_t)u * EMB))[lane];
    float2 b0 = ((const float2*)(ie + (size_t)iv * EMB))[lane];
    float2 b1 = ((const float2*)(g_e1 + (size_t)v * EMB))[lane];
    float2 b2 = ((const float2*)(g_e2 + (size_t)v * EMB))[lane];
    float2 b3 = ((const float2*)(g_e3 + (size_t)v * EMB))[lane];

    float ufx = w0 * a0.x + w1 * a1.x + w2 * a2.x + w3 * a3.x;
    float ufy = w0 * a0.y + w1 * a1.y + w2 * a2.y + w3 * a3.y;
    float vfx = w0 * b0.x + w1 * b1.x + w2 * b2.x + w3 * b3.x;
    float vfy = w0 * b0.y + w1 * b1.y + w2 * b2.y + w3 * b3.y;

    float acc = ufx * vfx + ufy * vfy;
    #pragma unroll
    for (int off = 16; off > 0; off >>= 1)
        acc += __shfl_down_sync(0xffffffffu, acc, off);
    if (lane == 0) out[gw] = acc;
}

// ------------------------- launcher --------------------------------
extern "C" void kernel_launch(void* const* d_in, const int* in_sizes, int n_in,
                              void* d_out, int out_size) {
    const float* user_emb = (const float*)d_in[0];
    const float* item_emb = (const float*)d_in[1];
    const float* layer_w  = (const float*)d_in[2];
    const int*   eu       = (const int*)d_in[3];
    const int*   ei       = (const int*)d_in[4];
    const int*   uids     = (const int*)d_in[5];
    const int*   iids     = (const int*)d_in[6];
    float*       out      = (float*)d_out;
    (void)in_sizes; (void)n_in; (void)out_size;

    float *e1, *e2, *e3;
    int *list2, *list3, *n2, *n3;
    cudaGetSymbolAddress((void**)&e1, g_e1);
    cudaGetSymbolAddress((void**)&e2, g_e2);
    cudaGetSymbolAddress((void**)&e3, g_e3);
    cudaGetSymbolAddress((void**)&list2, g_list2);
    cudaGetSymbolAddress((void**)&list3, g_list3);
    cudaGetSymbolAddress((void**)&n2, g_n2);
    cudaGetSymbolAddress((void**)&n3, g_n3);

    softmax_kernel<<<1, 1>>>(layer_w);

    // ---- CSR build + frontier marking ----
    zero_misc_kernel<<<(NN + 255) / 256, 256>>>();
    hist_kernel<<<(NE + 255) / 256, 256>>>(eu, ei);
    mark3_kernel<<<(BATCH + 255) / 256, 256>>>(uids, iids);
    scanA_kernel<<<NSB, SCAN_BS>>>();
    scanB_kernel<<<1, 512>>>();
    scanC_kernel<<<NSB, SCAN_BS>>>();
    fill_kernel<<<(NE + 255) / 256, 256>>>(eu, ei);
    compact3_kernel<<<(NN + 255) / 256, 256>>>();
    mark2_kernel<<<(MAXL3 * 32 + 255) / 256, 256>>>();
    compact2_kernel<<<(NN + 255) / 256, 256>>>();

    // ---- propagation ----
    const int FULL_BLOCKS = (((NN + 1) / 2) * 32 + 255) / 256;
    const int L3_BLOCKS   = (((MAXL3 + 1) / 2) * 32 + 255) / 256;
    prop_full_kernel<<<FULL_BLOCKS, 256>>>(user_emb, item_emb, e1);
    prop_list_kernel<<<FULL_BLOCKS, 256>>>(e1, e2, list2, n2);
    prop_list_kernel<<<L3_BLOCKS, 256>>>(e2, e3, list3, n3);

    // ---- scores ----
    score_kernel<<<(BATCH * 32 + 255) / 256, 256>>>(uids, iids, user_emb, item_emb, out);
}

// round 9
// speedup vs baseline: 2.6924x; 1.2160x over previous
#include <cuda_runtime.h>
#include <cuda_fp16.h>

#define NU 100000
#define NI 200000
#define NN 300000          // NU + NI
#define EMB 64
#define NE 1000000
#define BATCH 16384
#define MAXL3 (2 * BATCH)

#define SCAN_BS 1024
#define NSB ((NN + SCAN_BS - 1) / SCAN_BS)   // 293

// -------- scratch (device globals; no allocation allowed) ----------
__device__ int    g_cnt[NN];
__device__ int    g_scan[NN];
__device__ int    g_bsum[NSB];
__device__ int    g_boff[NSB];
__device__ int    g_off[NN + 1];
__device__ int    g_cursor[NN];
__device__ float  g_dinv[NN];
__device__ float  g_w[4];
__device__ float2 g_adj[2 * NE];           // {dst (int bits), edge weight}
__device__ __half g_h0[(size_t)NN * EMB];  // fp16 copy of inputs
__device__ __half g_h1[(size_t)NN * EMB];
__device__ __half g_h2[(size_t)NN * EMB];
__device__ __half g_h3[(size_t)NN * EMB];
__device__ int    g_flag2[NN];
__device__ int    g_flag3[NN];
__device__ int    g_list2[NN];
__device__ int    g_list3[MAXL3];
__device__ int    g_n2;
__device__ int    g_n3;

// -------------------- small kernels --------------------------------
__global__ void zero_misc_kernel() {
    int i = blockIdx.x * blockDim.x + threadIdx.x;
    if (i < NN) { g_cnt[i] = 0; g_flag2[i] = 0; g_flag3[i] = 0; }
    if (i == 0) { g_n2 = 0; g_n3 = 0; }
}

__global__ void softmax_kernel(const float* __restrict__ lw) {
    float m = lw[0];
    for (int i = 1; i < 4; i++) m = fmaxf(m, lw[i]);
    float s = 0.f, e[4];
    for (int i = 0; i < 4; i++) { e[i] = expf(lw[i] - m); s += e[i]; }
    for (int i = 0; i < 4; i++) g_w[i] = e[i] / s;
}

// fp32 inputs -> fp16 h0; each thread converts 8 floats (one uint4 of halves)
__global__ void conv_kernel(const float* __restrict__ ue,
                            const float* __restrict__ ie) {
    size_t i = (size_t)blockIdx.x * blockDim.x + threadIdx.x;
    const size_t total = (size_t)NN * EMB / 8;
    if (i >= total) return;
    size_t base = i * 8;
    const float4* s = (base < (size_t)NU * EMB)
        ? (const float4*)(ue + base)
        : (const float4*)(ie + (base - (size_t)NU * EMB));
    float4 a = s[0], b = s[1];
    __half2 h0 = __floats2half2_rn(a.x, a.y);
    __half2 h1 = __floats2half2_rn(a.z, a.w);
    __half2 h2 = __floats2half2_rn(b.x, b.y);
    __half2 h3 = __floats2half2_rn(b.z, b.w);
    uint4 o;
    o.x = *(unsigned*)&h0; o.y = *(unsigned*)&h1;
    o.z = *(unsigned*)&h2; o.w = *(unsigned*)&h3;
    ((uint4*)g_h0)[i] = o;
}

// fused degree histogram + batch-node marking
__global__ void hist_mark_kernel(const int* __restrict__ eu,
                                 const int* __restrict__ ei,
                                 const int* __restrict__ uids,
                                 const int* __restrict__ iids) {
    int i = blockIdx.x * blockDim.x + threadIdx.x;
    if (i < NE) {
        atomicAdd(&g_cnt[eu[i]], 1);
        atomicAdd(&g_cnt[NU + ei[i]], 1);
    } else {
        int j = i - NE;
        if (j < BATCH) {
            int u = uids[j];
            int v = NU + iids[j];
            g_flag3[u] = 1; g_flag3[v] = 1;
            g_flag2[u] = 1; g_flag2[v] = 1;
        }
    }
}

__global__ void scanA_kernel() {
    __shared__ int sh[SCAN_BS];
    int tid = threadIdx.x;
    int i = blockIdx.x * SCAN_BS + tid;
    int v = (i < NN) ? g_cnt[i] : 0;
    sh[tid] = v;
    __syncthreads();
    #pragma unroll
    for (int off = 1; off < SCAN_BS; off <<= 1) {
        int t = (tid >= off) ? sh[tid - off] : 0;
        __syncthreads();
        sh[tid] += t;
        __syncthreads();
    }
    if (i < NN) g_scan[i] = sh[tid];
    if (tid == SCAN_BS - 1) g_bsum[blockIdx.x] = sh[tid];
}

__global__ void scanB_kernel() {
    __shared__ int sh[512];
    int tid = threadIdx.x;
    int v = (tid < NSB) ? g_bsum[tid] : 0;
    sh[tid] = v;
    __syncthreads();
    #pragma unroll
    for (int off = 1; off < 512; off <<= 1) {
        int t = (tid >= off) ? sh[tid - off] : 0;
        __syncthreads();
        sh[tid] += t;
        __syncthreads();
    }
    if (tid < NSB) g_boff[tid] = sh[tid] - v;   // exclusive
}

__global__ void scanC_kernel() {
    int i = blockIdx.x * SCAN_BS + threadIdx.x;
    if (i >= NN) return;
    int c = g_cnt[i];
    int excl = g_scan[i] - c + g_boff[blockIdx.x];
    g_off[i] = excl;
    g_cursor[i] = excl;
    g_dinv[i] = (c > 0) ? rsqrtf((float)c) : 0.f;
    if (i == NN - 1) g_off[NN] = excl + c;
}

__global__ void fill_kernel(const int* __restrict__ eu,
                            const int* __restrict__ ei) {
    int i = blockIdx.x * blockDim.x + threadIdx.x;
    if (i >= NE) return;
    int u = eu[i];
    int v = NU + ei[i];
    float w = g_dinv[u] * g_dinv[v];
    int p = atomicAdd(&g_cursor[u], 1);
    g_adj[p] = make_float2(__int_as_float(v), w);
    int q = atomicAdd(&g_cursor[v], 1);
    g_adj[q] = make_float2(__int_as_float(u), w);
}

// ------------- frontier compaction ---------------------------------
__global__ void compact3_kernel() {
    int i = blockIdx.x * blockDim.x + threadIdx.x;
    if (i >= NN) return;
    if (g_flag3[i]) { int p = atomicAdd(&g_n3, 1); g_list3[p] = i; }
}

// mark neighbors of batch nodes directly (idempotent flag writes; skips
// the compact3 dependency). One warp per batch pair; half-warp per node.
__global__ void mark2_kernel(const int* __restrict__ uids,
                             const int* __restrict__ iids) {
    int idx = (blockIdx.x * blockDim.x + threadIdx.x) >> 5;
    if (idx >= BATCH) return;
    int lane = threadIdx.x & 31;
    int node = (lane < 16) ? uids[idx] : (NU + iids[idx]);
    int sub = lane & 15;
    int start = g_off[node], end = g_off[node + 1];
    for (int p = start + sub; p < end; p += 16) {
        int v = __float_as_int(g_adj[p].x);
        g_flag2[v] = 1;
    }
}

__global__ void compact2_kernel() {
    int i = blockIdx.x * blockDim.x + threadIdx.x;
    if (i >= NN) return;
    if (g_flag2[i]) { int p = atomicAdd(&g_n2, 1); g_list2[p] = i; }
}

// ---------------- fp16 gather propagation core ---------------------
// node handled by 8 lanes; each lane owns 8 dims (uint4 of half2).
// 4 nodes per warp. Inner loop unrolled by 4 -> 4 independent LDG.128.
__device__ __forceinline__ void acc_row(const __half* __restrict__ prevH,
                                        int v, int sub, float w, float* acc) {
    uint4 p = ((const uint4*)(prevH + (size_t)v * EMB))[sub];
    float2 f0 = __half22float2(*(__half2*)&p.x);
    float2 f1 = __half22float2(*(__half2*)&p.y);
    float2 f2 = __half22float2(*(__half2*)&p.z);
    float2 f3 = __half22float2(*(__half2*)&p.w);
    acc[0] += w * f0.x; acc[1] += w * f0.y;
    acc[2] += w * f1.x; acc[3] += w * f1.y;
    acc[4] += w * f2.x; acc[5] += w * f2.y;
    acc[6] += w * f3.x; acc[7] += w * f3.y;
}

__device__ __forceinline__ void gather8(int node, int sub, unsigned mask,
                                        const __half* __restrict__ prevH,
                                        __half* __restrict__ nextH) {
    int start = g_off[node];
    int end   = g_off[node + 1];
    float acc[8] = {0.f, 0.f, 0.f, 0.f, 0.f, 0.f, 0.f, 0.f};

    for (int base = start; base < end; base += 8) {
        int n = min(8, end - base);
        float2 e = make_float2(0.f, 0.f);
        if (sub < n) e = g_adj[base + sub];
        int   dr = __float_as_int(e.x);
        float wr = e.y;
        int j = 0;
        for (; j + 4 <= n; j += 4) {
            int   v0 = __shfl_sync(mask, dr, j + 0, 8);
            int   v1 = __shfl_sync(mask, dr, j + 1, 8);
            int   v2 = __shfl_sync(mask, dr, j + 2, 8);
            int   v3 = __shfl_sync(mask, dr, j + 3, 8);
            float w0 = __shfl_sync(mask, wr, j + 0, 8);
            float w1 = __shfl_sync(mask, wr, j + 1, 8);
            float w2 = __shfl_sync(mask, wr, j + 2, 8);
            float w3 = __shfl_sync(mask, wr, j + 3, 8);
            uint4 p0 = ((const uint4*)(prevH + (size_t)v0 * EMB))[sub];
            uint4 p1 = ((const uint4*)(prevH + (size_t)v1 * EMB))[sub];
            uint4 p2 = ((const uint4*)(prevH + (size_t)v2 * EMB))[sub];
            uint4 p3 = ((const uint4*)(prevH + (size_t)v3 * EMB))[sub];
            {
                float2 f0 = __half22float2(*(__half2*)&p0.x);
                float2 f1 = __half22float2(*(__half2*)&p0.y);
                float2 f2 = __half22float2(*(__half2*)&p0.z);
                float2 f3 = __half22float2(*(__half2*)&p0.w);
                acc[0] += w0 * f0.x; acc[1] += w0 * f0.y;
                acc[2] += w0 * f1.x; acc[3] += w0 * f1.y;
                acc[4] += w0 * f2.x; acc[5] += w0 * f2.y;
                acc[6] += w0 * f3.x; acc[7] += w0 * f3.y;
            }
            {
                float2 f0 = __half22float2(*(__half2*)&p1.x);
                float2 f1 = __half22float2(*(__half2*)&p1.y);
                float2 f2 = __half22float2(*(__half2*)&p1.z);
                float2 f3 = __half22float2(*(__half2*)&p1.w);
                acc[0] += w1 * f0.x; acc[1] += w1 * f0.y;
                acc[2] += w1 * f1.x; acc[3] += w1 * f1.y;
                acc[4] += w1 * f2.x; acc[5] += w1 * f2.y;
                acc[6] += w1 * f3.x; acc[7] += w1 * f3.y;
            }
            {
                float2 f0 = __half22float2(*(__half2*)&p2.x);
                float2 f1 = __half22float2(*(__half2*)&p2.y);
                float2 f2 = __half22float2(*(__half2*)&p2.z);
                float2 f3 = __half22float2(*(__half2*)&p2.w);
                acc[0] += w2 * f0.x; acc[1] += w2 * f0.y;
                acc[2] += w2 * f1.x; acc[3] += w2 * f1.y;
                acc[4] += w2 * f2.x; acc[5] += w2 * f2.y;
                acc[6] += w2 * f3.x; acc[7] += w2 * f3.y;
            }
            {
                float2 f0 = __half22float2(*(__half2*)&p3.x);
                float2 f1 = __half22float2(*(__half2*)&p3.y);
                float2 f2 = __half22float2(*(__half2*)&p3.z);
                float2 f3 = __half22float2(*(__half2*)&p3.w);
                acc[0] += w3 * f0.x; acc[1] += w3 * f0.y;
                acc[2] += w3 * f1.x; acc[3] += w3 * f1.y;
                acc[4] += w3 * f2.x; acc[5] += w3 * f2.y;
                acc[6] += w3 * f3.x; acc[7] += w3 * f3.y;
            }
        }
        for (; j < n; j++) {
            int   v = __shfl_sync(mask, dr, j, 8);
            float w = __shfl_sync(mask, wr, j, 8);
            acc_row(prevH, v, sub, w, acc);
        }
    }

    __half2 o0 = __floats2half2_rn(acc[0], acc[1]);
    __half2 o1 = __floats2half2_rn(acc[2], acc[3]);
    __half2 o2 = __floats2half2_rn(acc[4], acc[5]);
    __half2 o3 = __floats2half2_rn(acc[6], acc[7]);
    uint4 o;
    o.x = *(unsigned*)&o0; o.y = *(unsigned*)&o1;
    o.z = *(unsigned*)&o2; o.w = *(unsigned*)&o3;
    ((uint4*)(nextH + (size_t)node * EMB))[sub] = o;
}

__global__ void prop_full_kernel(const __half* __restrict__ prevH,
                                 __half* __restrict__ nextH) {
    int warpId = (blockIdx.x * blockDim.x + threadIdx.x) >> 5;
    int lane = threadIdx.x & 31;
    int quad = lane >> 3;
    int sub  = lane & 7;
    int node = warpId * 4 + quad;
    if (node >= NN) return;
    unsigned mask = 0xFFu << (quad * 8);
    gather8(node, sub, mask, prevH, nextH);
}

__global__ void prop_list_kernel(const __half* __restrict__ prevH,
                                 __half* __restrict__ nextH,
                                 const int* __restrict__ list,
                                 const int* __restrict__ count) {
    int warpId = (blockIdx.x * blockDim.x + threadIdx.x) >> 5;
    int lane = threadIdx.x & 31;
    int cnt = __shfl_sync(0xffffffffu, (lane == 0) ? *count : 0, 0);
    int quad = lane >> 3;
    int sub  = lane & 7;
    int idx = warpId * 4 + quad;
    if (idx >= cnt) return;
    int node = list[idx];
    unsigned mask = 0xFFu << (quad * 8);
    gather8(node, sub, mask, prevH, nextH);
}

// one warp per (user, item) pair; lane owns 2 dims
__global__ void score_kernel(const int* __restrict__ uids,
                             const int* __restrict__ iids,
                             const float* __restrict__ ue,
                             const float* __restrict__ ie,
                             float* __restrict__ out) {
    int gw = (blockIdx.x * blockDim.x + threadIdx.x) >> 5;
    if (gw >= BATCH) return;
    int lane = threadIdx.x & 31;
    int u = uids[gw];
    int iv = iids[gw];
    int v = NU + iv;

    float w0 = g_w[0], w1 = g_w[1], w2 = g_w[2], w3 = g_w[3];

    float2 a0 = ((const float2*)(ue + (size_t)u * EMB))[lane];
    float2 a1 = __half22float2(((const __half2*)(g_h1 + (size_t)u * EMB))[lane]);
    float2 a2 = __half22float2(((const __half2*)(g_h2 + (size_t)u * EMB))[lane]);
    float2 a3 = __half22float2(((const __half2*)(g_h3 + (size_t)u * EMB))[lane]);
    float2 b0 = ((const float2*)(ie + (size_t)iv * EMB))[lane];
    float2 b1 = __half22float2(((const __half2*)(g_h1 + (size_t)v * EMB))[lane]);
    float2 b2 = __half22float2(((const __half2*)(g_h2 + (size_t)v * EMB))[lane]);
    float2 b3 = __half22float2(((const __half2*)(g_h3 + (size_t)v * EMB))[lane]);

    float ufx = w0 * a0.x + w1 * a1.x + w2 * a2.x + w3 * a3.x;
    float ufy = w0 * a0.y + w1 * a1.y + w2 * a2.y + w3 * a3.y;
    float vfx = w0 * b0.x + w1 * b1.x + w2 * b2.x + w3 * b3.x;
    float vfy = w0 * b0.y + w1 * b1.y + w2 * b2.y + w3 * b3.y;

    float acc = ufx * vfx + ufy * vfy;
    #pragma unroll
    for (int off = 16; off > 0; off >>= 1)
        acc += __shfl_down_sync(0xffffffffu, acc, off);
    if (lane == 0) out[gw] = acc;
}

// ------------------------- launcher --------------------------------
extern "C" void kernel_launch(void* const* d_in, const int* in_sizes, int n_in,
                              void* d_out, int out_size) {
    const float* user_emb = (const float*)d_in[0];
    const float* item_emb = (const float*)d_in[1];
    const float* layer_w  = (const float*)d_in[2];
    const int*   eu       = (const int*)d_in[3];
    const int*   ei       = (const int*)d_in[4];
    const int*   uids     = (const int*)d_in[5];
    const int*   iids     = (const int*)d_in[6];
    float*       out      = (float*)d_out;
    (void)in_sizes; (void)n_in; (void)out_size;

    __half *h0, *h1, *h2, *h3;
    int *list2, *list3, *n2, *n3;
    cudaGetSymbolAddress((void**)&h0, g_h0);
    cudaGetSymbolAddress((void**)&h1, g_h1);
    cudaGetSymbolAddress((void**)&h2, g_h2);
    cudaGetSymbolAddress((void**)&h3, g_h3);
    cudaGetSymbolAddress((void**)&list2, g_list2);
    cudaGetSymbolAddress((void**)&list3, g_list3);
    cudaGetSymbolAddress((void**)&n2, g_n2);
    cudaGetSymbolAddress((void**)&n3, g_n3);

    softmax_kernel<<<1, 1>>>(layer_w);
    zero_misc_kernel<<<(NN + 255) / 256, 256>>>();

    // fp16 input conversion (independent of CSR chain)
    const size_t CONV_T = (size_t)NN * EMB / 8;
    conv_kernel<<<(int)((CONV_T + 255) / 256), 256>>>(user_emb, item_emb);

    // ---- CSR build + frontier marking ----
    hist_mark_kernel<<<(NE + BATCH + 255) / 256, 256>>>(eu, ei, uids, iids);
    scanA_kernel<<<NSB, SCAN_BS>>>();
    scanB_kernel<<<1, 512>>>();
    scanC_kernel<<<NSB, SCAN_BS>>>();
    fill_kernel<<<(NE + 255) / 256, 256>>>(eu, ei);
    compact3_kernel<<<(NN + 255) / 256, 256>>>();
    mark2_kernel<<<(BATCH * 32 + 255) / 256, 256>>>(uids, iids);
    compact2_kernel<<<(NN + 255) / 256, 256>>>();

    // ---- propagation (fp16 gathers, fp32 accumulate) ----
    const int FULL_BLOCKS = ((NN + 3) / 4 * 32 + 255) / 256;
    const int L3_BLOCKS   = ((MAXL3 + 3) / 4 * 32 + 255) / 256;
    prop_full_kernel<<<FULL_BLOCKS, 256>>>(h0, h1);
    prop_list_kernel<<<FULL_BLOCKS, 256>>>(h1, h2, list2, n2);
    prop_list_kernel<<<L3_BLOCKS, 256>>>(h2, h3, list3, n3);

    // ---- scores ----
    score_kernel<<<(BATCH * 32 + 255) / 256, 256>>>(uids, iids, user_emb, item_emb, out);
}

// round 10
// speedup vs baseline: 2.7887x; 1.0358x over previous
#include <cuda_runtime.h>
#include <cuda_fp16.h>

#define NU 100000
#define NI 200000
#define NN 300000          // NU + NI
#define EMB 64
#define NE 1000000
#define BATCH 16384

#define SCAN_BS 1024
#define NSB ((NN + SCAN_BS - 1) / SCAN_BS)   // 293

// -------- scratch (device globals; no allocation allowed) ----------
__device__ int    g_cnt[NN];
__device__ int    g_scan[NN];
__device__ int    g_bsum[NSB];
__device__ int    g_boff[NSB];
__device__ int    g_off[NN + 1];
__device__ int    g_cursor[NN];
__device__ float  g_dinv[NN];
__device__ float  g_w[4];
__device__ float2 g_adj[2 * NE];           // {dst (int bits), edge weight}
__device__ __half g_h0[(size_t)NN * EMB];  // fp16 inputs
__device__ __half g_h1[(size_t)NN * EMB];  // layer 1
__device__ __half g_h2[(size_t)NN * EMB];  // layer 2
__device__ int    g_flag2[NN];
__device__ int    g_list2[NN];
__device__ int    g_n2;

// ---------------- fused init: softmax + zero + fp32->fp16 conv -----
__global__ void init_kernel(const float* __restrict__ ue,
                            const float* __restrict__ ie,
                            const float* __restrict__ lw) {
    size_t i = (size_t)blockIdx.x * blockDim.x + threadIdx.x;
    const size_t total = (size_t)NN * EMB / 8;
    if (i < total) {
        size_t base = i * 8;
        const float4* s = (base < (size_t)NU * EMB)
            ? (const float4*)(ue + base)
            : (const float4*)(ie + (base - (size_t)NU * EMB));
        float4 a = s[0], b = s[1];
        __half2 c0 = __floats2half2_rn(a.x, a.y);
        __half2 c1 = __floats2half2_rn(a.z, a.w);
        __half2 c2 = __floats2half2_rn(b.x, b.y);
        __half2 c3 = __floats2half2_rn(b.z, b.w);
        uint4 o;
        o.x = *(unsigned*)&c0; o.y = *(unsigned*)&c1;
        o.z = *(unsigned*)&c2; o.w = *(unsigned*)&c3;
        ((uint4*)g_h0)[i] = o;
    }
    if (i < NN) { g_cnt[i] = 0; g_flag2[i] = 0; }
    if (i == 0) {
        g_n2 = 0;
        float m = lw[0];
        for (int k = 1; k < 4; k++) m = fmaxf(m, lw[k]);
        float s = 0.f, e[4];
        for (int k = 0; k < 4; k++) { e[k] = expf(lw[k] - m); s += e[k]; }
        for (int k = 0; k < 4; k++) g_w[k] = e[k] / s;
    }
}

// ---------------- degree histogram (int4-vectorized) ---------------
__global__ void hist_kernel(const int* __restrict__ eu,
                            const int* __restrict__ ei) {
    int i = blockIdx.x * blockDim.x + threadIdx.x;
    if (i >= NE / 4) return;
    int4 a = ((const int4*)eu)[i];
    int4 b = ((const int4*)ei)[i];
    atomicAdd(&g_cnt[a.x], 1);
    atomicAdd(&g_cnt[a.y], 1);
    atomicAdd(&g_cnt[a.z], 1);
    atomicAdd(&g_cnt[a.w], 1);
    atomicAdd(&g_cnt[NU + b.x], 1);
    atomicAdd(&g_cnt[NU + b.y], 1);
    atomicAdd(&g_cnt[NU + b.z], 1);
    atomicAdd(&g_cnt[NU + b.w], 1);
}

// ---------------- scans --------------------------------------------
__global__ void scanA_kernel() {
    __shared__ int ws[32];
    int tid = threadIdx.x;
    int i = blockIdx.x * SCAN_BS + tid;
    int lane = tid & 31, wid = tid >> 5;
    int v = (i < NN) ? g_cnt[i] : 0;
    int x = v;
    #pragma unroll
    for (int off = 1; off < 32; off <<= 1) {
        int t = __shfl_up_sync(0xffffffffu, x, off);
        if (lane >= off) x += t;
    }
    if (lane == 31) ws[wid] = x;
    __syncthreads();
    if (wid == 0) {
        int y = ws[lane];
        #pragma unroll
        for (int off = 1; off < 32; off <<= 1) {
            int t = __shfl_up_sync(0xffffffffu, y, off);
            if (lane >= off) y += t;
        }
        ws[lane] = y;
    }
    __syncthreads();
    if (wid > 0) x += ws[wid - 1];
    if (i < NN) g_scan[i] = x;
    if (tid == SCAN_BS - 1) g_bsum[blockIdx.x] = x;
}

__global__ void scanB_kernel() {
    __shared__ int sh[512];
    int tid = threadIdx.x;
    int v = (tid < NSB) ? g_bsum[tid] : 0;
    sh[tid] = v;
    __syncthreads();
    #pragma unroll
    for (int off = 1; off < 512; off <<= 1) {
        int t = (tid >= off) ? sh[tid - off] : 0;
        __syncthreads();
        sh[tid] += t;
        __syncthreads();
    }
    if (tid < NSB) g_boff[tid] = sh[tid] - v;   // exclusive
}

__global__ void scanC_kernel() {
    int i = blockIdx.x * SCAN_BS + threadIdx.x;
    if (i >= NN) return;
    int c = g_cnt[i];
    int excl = g_scan[i] - c + g_boff[blockIdx.x];
    g_off[i] = excl;
    g_cursor[i] = excl;
    g_dinv[i] = (c > 0) ? rsqrtf((float)c) : 0.f;
    if (i == NN - 1) g_off[NN] = excl + c;
}

__global__ void fill_kernel(const int* __restrict__ eu,
                            const int* __restrict__ ei) {
    int i = blockIdx.x * blockDim.x + threadIdx.x;
    if (i >= NE) return;
    int u = eu[i];
    int v = NU + ei[i];
    float w = g_dinv[u] * g_dinv[v];
    int p = atomicAdd(&g_cursor[u], 1);
    g_adj[p] = make_float2(__int_as_float(v), w);
    int q = atomicAdd(&g_cursor[v], 1);
    g_adj[q] = make_float2(__int_as_float(u), w);
}

// mark neighbors of batch nodes (need e2 there). warp per pair.
__global__ void mark2_kernel(const int* __restrict__ uids,
                             const int* __restrict__ iids) {
    int idx = (blockIdx.x * blockDim.x + threadIdx.x) >> 5;
    if (idx >= BATCH) return;
    int lane = threadIdx.x & 31;
    int node = (lane < 16) ? uids[idx] : (NU + iids[idx]);
    int sub = lane & 15;
    int start = g_off[node], end = g_off[node + 1];
    for (int p = start + sub; p < end; p += 16) {
        int v = __float_as_int(g_adj[p].x);
        g_flag2[v] = 1;
    }
    // batch nodes themselves also need e2 (score does layer-3 gather FROM e2,
    // but u/v themselves aren't read from e2... they ARE read: h2 row of node
    // in layer-2 term of final). mark them too:
    if (sub == 0) g_flag2[node] = 1;
}

__global__ void compact2_kernel() {
    int i = blockIdx.x * blockDim.x + threadIdx.x;
    if (i >= NN) return;
    if (g_flag2[i]) { int p = atomicAdd(&g_n2, 1); g_list2[p] = i; }
}

// ---------------- fp16 gather core (8 lanes/node, uint4/lane) ------
__device__ __forceinline__ void acc_row8(const __half* __restrict__ prevH,
                                         int v, int sub, float w, float* acc) {
    uint4 p = ((const uint4*)(prevH + (size_t)v * EMB))[sub];
    float2 f0 = __half22float2(*(__half2*)&p.x);
    float2 f1 = __half22float2(*(__half2*)&p.y);
    float2 f2 = __half22float2(*(__half2*)&p.z);
    float2 f3 = __half22float2(*(__half2*)&p.w);
    acc[0] += w * f0.x; acc[1] += w * f0.y;
    acc[2] += w * f1.x; acc[3] += w * f1.y;
    acc[4] += w * f2.x; acc[5] += w * f2.y;
    acc[6] += w * f3.x; acc[7] += w * f3.y;
}

__device__ __forceinline__ void gather8(int node, int sub, unsigned mask,
                                        const __half* __restrict__ prevH,
                                        float* acc) {
    int start = g_off[node];
    int end   = g_off[node + 1];
    for (int base = start; base < end; base += 8) {
        int n = min(8, end - base);
        float2 e = make_float2(0.f, 0.f);
        if (sub < n) e = g_adj[base + sub];
        int   dr = __float_as_int(e.x);
        float wr = e.y;
        int j = 0;
        for (; j + 4 <= n; j += 4) {
            int   v0 = __shfl_sync(mask, dr, j + 0, 8);
            int   v1 = __shfl_sync(mask, dr, j + 1, 8);
            int   v2 = __shfl_sync(mask, dr, j + 2, 8);
            int   v3 = __shfl_sync(mask, dr, j + 3, 8);
            float w0 = __shfl_sync(mask, wr, j + 0, 8);
            float w1 = __shfl_sync(mask, wr, j + 1, 8);
            float w2 = __shfl_sync(mask, wr, j + 2, 8);
            float w3 = __shfl_sync(mask, wr, j + 3, 8);
            uint4 p0 = ((const uint4*)(prevH + (size_t)v0 * EMB))[sub];
            uint4 p1 = ((const uint4*)(prevH + (size_t)v1 * EMB))[sub];
            uint4 p2 = ((const uint4*)(prevH + (size_t)v2 * EMB))[sub];
            uint4 p3 = ((const uint4*)(prevH + (size_t)v3 * EMB))[sub];
            {
                float2 f0 = __half22float2(*(__half2*)&p0.x);
                float2 f1 = __half22float2(*(__half2*)&p0.y);
                float2 f2 = __half22float2(*(__half2*)&p0.z);
                float2 f3 = __half22float2(*(__half2*)&p0.w);
                acc[0] += w0 * f0.x; acc[1] += w0 * f0.y;
                acc[2] += w0 * f1.x; acc[3] += w0 * f1.y;
                acc[4] += w0 * f2.x; acc[5] += w0 * f2.y;
                acc[6] += w0 * f3.x; acc[7] += w0 * f3.y;
            }
            {
                float2 f0 = __half22float2(*(__half2*)&p1.x);
                float2 f1 = __half22float2(*(__half2*)&p1.y);
                float2 f2 = __half22float2(*(__half2*)&p1.z);
                float2 f3 = __half22float2(*(__half2*)&p1.w);
                acc[0] += w1 * f0.x; acc[1] += w1 * f0.y;
                acc[2] += w1 * f1.x; acc[3] += w1 * f1.y;
                acc[4] += w1 * f2.x; acc[5] += w1 * f2.y;
                acc[6] += w1 * f3.x; acc[7] += w1 * f3.y;
            }
            {
                float2 f0 = __half22float2(*(__half2*)&p2.x);
                float2 f1 = __half22float2(*(__half2*)&p2.y);
                float2 f2 = __half22float2(*(__half2*)&p2.z);
                float2 f3 = __half22float2(*(__half2*)&p2.w);
                acc[0] += w2 * f0.x; acc[1] += w2 * f0.y;
                acc[2] += w2 * f1.x; acc[3] += w2 * f1.y;
                acc[4] += w2 * f2.x; acc[5] += w2 * f2.y;
                acc[6] += w2 * f3.x; acc[7] += w2 * f3.y;
            }
            {
                float2 f0 = __half22float2(*(__half2*)&p3.x);
                float2 f1 = __half22float2(*(__half2*)&p3.y);
                float2 f2 = __half22float2(*(__half2*)&p3.z);
                float2 f3 = __half22float2(*(__half2*)&p3.w);
                acc[0] += w3 * f0.x; acc[1] += w3 * f0.y;
                acc[2] += w3 * f1.x; acc[3] += w3 * f1.y;
                acc[4] += w3 * f2.x; acc[5] += w3 * f2.y;
                acc[6] += w3 * f3.x; acc[7] += w3 * f3.y;
            }
        }
        for (; j < n; j++) {
            int   v = __shfl_sync(mask, dr, j, 8);
            float w = __shfl_sync(mask, wr, j, 8);
            acc_row8(prevH, v, sub, w, acc);
        }
    }
}

__device__ __forceinline__ void store_half8(__half* __restrict__ nextH,
                                            int node, int sub, const float* acc) {
    __half2 o0 = __floats2half2_rn(acc[0], acc[1]);
    __half2 o1 = __floats2half2_rn(acc[2], acc[3]);
    __half2 o2 = __floats2half2_rn(acc[4], acc[5]);
    __half2 o3 = __floats2half2_rn(acc[6], acc[7]);
    uint4 o;
    o.x = *(unsigned*)&o0; o.y = *(unsigned*)&o1;
    o.z = *(unsigned*)&o2; o.w = *(unsigned*)&o3;
    ((uint4*)(nextH + (size_t)node * EMB))[sub] = o;
}

__global__ void prop_full_kernel(const __half* __restrict__ prevH,
                                 __half* __restrict__ nextH) {
    int warpId = (blockIdx.x * blockDim.x + threadIdx.x) >> 5;
    int lane = threadIdx.x & 31;
    int quad = lane >> 3;
    int sub  = lane & 7;
    int node = warpId * 4 + quad;
    if (node >= NN) return;
    unsigned mask = 0xFFu << (quad * 8);
    float acc[8] = {0.f,0.f,0.f,0.f,0.f,0.f,0.f,0.f};
    gather8(node, sub, mask, prevH, acc);
    store_half8(nextH, node, sub, acc);
}

__global__ void prop_list_kernel(const __half* __restrict__ prevH,
                                 __half* __restrict__ nextH,
                                 const int* __restrict__ list,
                                 const int* __restrict__ count) {
    int warpId = (blockIdx.x * blockDim.x + threadIdx.x) >> 5;
    int lane = threadIdx.x & 31;
    int cnt = __shfl_sync(0xffffffffu, (lane == 0) ? *count : 0, 0);
    int quad = lane >> 3;
    int sub  = lane & 7;
    int idx = warpId * 4 + quad;
    if (idx >= cnt) return;
    int node = list[idx];
    unsigned mask = 0xFFu << (quad * 8);
    float acc[8] = {0.f,0.f,0.f,0.f,0.f,0.f,0.f,0.f};
    gather8(node, sub, mask, prevH, acc);
    store_half8(nextH, node, sub, acc);
}

// --------------- fused layer-3 + score -----------------------------
// 8 lanes per node-side, 2 sides per pair, 4 sides per warp.
// side final vec (64 dims, 8/lane): w0*in + w1*h1 + w2*h2 + w3*gather(h2).
// Dot via shfl_xor(8) partner exchange, reduce within 8 lanes.
__global__ void score_kernel(const int* __restrict__ uids,
                             const int* __restrict__ iids,
                             const float* __restrict__ ue,
                             const float* __restrict__ ie,
                             float* __restrict__ out) {
    int gt = blockIdx.x * blockDim.x + threadIdx.x;
    int grpG = gt >> 3;
    int sub  = gt & 7;
    int pair = grpG >> 1;
    int side = grpG & 1;
    if (pair >= BATCH) return;       // exact grid: never taken
    int lane = threadIdx.x & 31;
    int grp = lane >> 3;
    unsigned gmask = 0xFFu << (grp * 8);

    int node;
    const float4* r0;
    if (side == 0) {
        int u = uids[pair];
        node = u;
        r0 = (const float4*)(ue + (size_t)u * EMB);
    } else {
        int v = iids[pair];
        node = NU + v;
        r0 = (const float4*)(ie + (size_t)v * EMB);
    }

    float w0 = g_w[0], w1 = g_w[1], w2 = g_w[2], w3 = g_w[3];

    // layer-3 gather over h2
    float a3[8] = {0.f,0.f,0.f,0.f,0.f,0.f,0.f,0.f};
    gather8(node, sub, gmask, g_h2, a3);

    // layers 0,1,2 rows for this node
    float4 pa = r0[sub * 2];
    float4 pb = r0[sub * 2 + 1];
    uint4 x1 = ((const uint4*)(g_h1 + (size_t)node * EMB))[sub];
    uint4 x2 = ((const uint4*)(g_h2 + (size_t)node * EMB))[sub];
    float2 l1a = __half22float2(*(__half2*)&x1.x);
    float2 l1b = __half22float2(*(__half2*)&x1.y);
    float2 l1c = __half22float2(*(__half2*)&x1.z);
    float2 l1d = __half22float2(*(__half2*)&x1.w);
    float2 l2a = __half22float2(*(__half2*)&x2.x);
    float2 l2b = __half22float2(*(__half2*)&x2.y);
    float2 l2c = __half22float2(*(__half2*)&x2.z);
    float2 l2d = __half22float2(*(__half2*)&x2.w);

    float f[8];
    f[0] = w0 * pa.x + w1 * l1a.x + w2 * l2a.x + w3 * a3[0];
    f[1] = w0 * pa.y + w1 * l1a.y + w2 * l2a.y + w3 * a3[1];
    f[2] = w0 * pa.z + w1 * l1b.x + w2 * l2b.x + w3 * a3[2];
    f[3] = w0 * pa.w + w1 * l1b.y + w2 * l2b.y + w3 * a3[3];
    f[4] = w0 * pb.x + w1 * l1c.x + w2 * l2c.x + w3 * a3[4];
    f[5] = w0 * pb.y + w1 * l1c.y + w2 * l2c.y + w3 * a3[5];
    f[6] = w0 * pb.z + w1 * l1d.x + w2 * l2d.x + w3 * a3[6];
    f[7] = w0 * pb.w + w1 * l1d.y + w2 * l2d.y + w3 * a3[7];

    // exchange with partner side (lane ^ 8) and dot
    float dp = 0.f;
    #pragma unroll
    for (int k = 0; k < 8; k++) {
        float other = __shfl_xor_sync(0xffffffffu, f[k], 8);
        dp += f[k] * other;
    }
    dp += __shfl_down_sync(0xffffffffu, dp, 4, 8);
    dp += __shfl_down_sync(0xffffffffu, dp, 2, 8);
    dp += __shfl_down_sync(0xffffffffu, dp, 1, 8);
    if (side == 0 && sub == 0) out[pair] = dp;
}

// ------------------------- launcher --------------------------------
extern "C" void kernel_launch(void* const* d_in, const int* in_sizes, int n_in,
                              void* d_out, int out_size) {
    const float* user_emb = (const float*)d_in[0];
    const float* item_emb = (const float*)d_in[1];
    const float* layer_w  = (const float*)d_in[2];
    const int*   eu       = (const int*)d_in[3];
    const int*   ei       = (const int*)d_in[4];
    const int*   uids     = (const int*)d_in[5];
    const int*   iids     = (const int*)d_in[6];
    float*       out      = (float*)d_out;
    (void)in_sizes; (void)n_in; (void)out_size;

    __half *h0, *h1, *h2;
    int *list2, *n2;
    cudaGetSymbolAddress((void**)&h0, g_h0);
    cudaGetSymbolAddress((void**)&h1, g_h1);
    cudaGetSymbolAddress((void**)&h2, g_h2);
    cudaGetSymbolAddress((void**)&list2, g_list2);
    cudaGetSymbolAddress((void**)&n2, g_n2);

    // init: softmax + zero counters/flags + fp16 conversion
    const size_t CONV_T = (size_t)NN * EMB / 8;
    init_kernel<<<(int)((CONV_T + 255) / 256), 256>>>(user_emb, item_emb, layer_w);

    // ---- CSR build + frontier ----
    hist_kernel<<<(NE / 4 + 255) / 256, 256>>>(eu, ei);
    scanA_kernel<<<NSB, SCAN_BS>>>();
    scanB_kernel<<<1, 512>>>();
    scanC_kernel<<<NSB, SCAN_BS>>>();
    fill_kernel<<<(NE + 255) / 256, 256>>>(eu, ei);
    mark2_kernel<<<(BATCH * 32 + 255) / 256, 256>>>(uids, iids);
    compact2_kernel<<<(NN + 255) / 256, 256>>>();

    // ---- propagation (fp16 gathers, fp32 accumulate) ----
    const int FULL_BLOCKS = ((NN + 3) / 4 * 32 + 255) / 256;
    prop_full_kernel<<<FULL_BLOCKS, 256>>>(h0, h1);
    prop_list_kernel<<<FULL_BLOCKS, 256>>>(h1, h2, list2, n2);

    // ---- fused layer-3 + scores ----
    score_kernel<<<(BATCH * 16 + 255) / 256, 256>>>(uids, iids, user_emb, item_emb, out);
}

// round 11
// speedup vs baseline: 2.9372x; 1.0532x over previous
#include <cuda_runtime.h>
#include <cuda_fp16.h>

#define NU 100000
#define NI 200000
#define NN 300000          // NU + NI
#define EMB 64
#define NE 1000000
#define BATCH 16384

#define SCAN_BS 1024
#define NSB ((NN + SCAN_BS - 1) / SCAN_BS)   // 293

// -------- scratch (device globals; no allocation allowed) ----------
__device__ int    g_cnt[NN];
__device__ int    g_scan[NN];
__device__ int    g_bsum[NSB];
__device__ int    g_off[NN + 1];
__device__ int    g_cursor[NN];
__device__ float  g_dinv[NN];
__device__ float  g_w[4];
__device__ float2 g_adj[2 * NE];           // {dst (int bits), edge weight}
__device__ __half g_h0[(size_t)NN * EMB];  // fp16 inputs
__device__ __half g_h1[(size_t)NN * EMB];  // layer 1
__device__ __half g_h2[(size_t)NN * EMB];  // layer 2
__device__ int    g_flag2[NN];
__device__ int    g_list2[NN];
__device__ int    g_n2;

// ---------------- zero + softmax (critical path head) --------------
__global__ void zero_kernel(const float* __restrict__ lw) {
    int i = blockIdx.x * blockDim.x + threadIdx.x;
    if (i < NN) { g_cnt[i] = 0; g_flag2[i] = 0; }
    if (i == 0) {
        g_n2 = 0;
        float m = lw[0];
        for (int k = 1; k < 4; k++) m = fmaxf(m, lw[k]);
        float s = 0.f, e[4];
        for (int k = 0; k < 4; k++) { e[k] = expf(lw[k] - m); s += e[k]; }
        for (int k = 0; k < 4; k++) g_w[k] = e[k] / s;
    }
}

// ---------------- fp32 -> fp16 conversion (side stream) ------------
__global__ void conv_kernel(const float* __restrict__ ue,
                            const float* __restrict__ ie) {
    size_t i = (size_t)blockIdx.x * blockDim.x + threadIdx.x;
    const size_t total = (size_t)NN * EMB / 8;
    if (i >= total) return;
    size_t base = i * 8;
    const float4* s = (base < (size_t)NU * EMB)
        ? (const float4*)(ue + base)
        : (const float4*)(ie + (base - (size_t)NU * EMB));
    float4 a = s[0], b = s[1];
    __half2 c0 = __floats2half2_rn(a.x, a.y);
    __half2 c1 = __floats2half2_rn(a.z, a.w);
    __half2 c2 = __floats2half2_rn(b.x, b.y);
    __half2 c3 = __floats2half2_rn(b.z, b.w);
    uint4 o;
    o.x = *(unsigned*)&c0; o.y = *(unsigned*)&c1;
    o.z = *(unsigned*)&c2; o.w = *(unsigned*)&c3;
    ((uint4*)g_h0)[i] = o;
}

// ---------------- degree histogram (int4-vectorized) ---------------
__global__ void hist_kernel(const int* __restrict__ eu,
                            const int* __restrict__ ei) {
    int i = blockIdx.x * blockDim.x + threadIdx.x;
    if (i >= NE / 4) return;
    int4 a = ((const int4*)eu)[i];
    int4 b = ((const int4*)ei)[i];
    atomicAdd(&g_cnt[a.x], 1);
    atomicAdd(&g_cnt[a.y], 1);
    atomicAdd(&g_cnt[a.z], 1);
    atomicAdd(&g_cnt[a.w], 1);
    atomicAdd(&g_cnt[NU + b.x], 1);
    atomicAdd(&g_cnt[NU + b.y], 1);
    atomicAdd(&g_cnt[NU + b.z], 1);
    atomicAdd(&g_cnt[NU + b.w], 1);
}

// ---------------- scans --------------------------------------------
__global__ void scanA_kernel() {
    __shared__ int ws[32];
    int tid = threadIdx.x;
    int i = blockIdx.x * SCAN_BS + tid;
    int lane = tid & 31, wid = tid >> 5;
    int v = (i < NN) ? g_cnt[i] : 0;
    int x = v;
    #pragma unroll
    for (int off = 1; off < 32; off <<= 1) {
        int t = __shfl_up_sync(0xffffffffu, x, off);
        if (lane >= off) x += t;
    }
    if (lane == 31) ws[wid] = x;
    __syncthreads();
    if (wid == 0) {
        int y = ws[lane];
        #pragma unroll
        for (int off = 1; off < 32; off <<= 1) {
            int t = __shfl_up_sync(0xffffffffu, y, off);
            if (lane >= off) y += t;
        }
        ws[lane] = y;
    }
    __syncthreads();
    if (wid > 0) x += ws[wid - 1];
    if (i < NN) g_scan[i] = x;
    if (tid == SCAN_BS - 1) g_bsum[blockIdx.x] = x;
}

// scanC with inline block-offset: warp 0 reduces g_bsum[0..blockIdx)
__global__ void scanC_kernel() {
    __shared__ int s_boff;
    int tid = threadIdx.x;
    if (tid < 32) {
        int sum = 0;
        for (int k = tid; k < blockIdx.x; k += 32) sum += g_bsum[k];
        #pragma unroll
        for (int off = 16; off > 0; off >>= 1)
            sum += __shfl_down_sync(0xffffffffu, sum, off);
        if (tid == 0) s_boff = sum;
    }
    __syncthreads();
    int i = blockIdx.x * SCAN_BS + tid;
    if (i >= NN) return;
    int c = g_cnt[i];
    int excl = g_scan[i] - c + s_boff;
    g_off[i] = excl;
    g_cursor[i] = excl;
    g_dinv[i] = (c > 0) ? rsqrtf((float)c) : 0.f;
    if (i == NN - 1) g_off[NN] = excl + c;
}

__global__ void fill_kernel(const int* __restrict__ eu,
                            const int* __restrict__ ei) {
    int i = blockIdx.x * blockDim.x + threadIdx.x;
    if (i >= NE) return;
    int u = eu[i];
    int v = NU + ei[i];
    float w = g_dinv[u] * g_dinv[v];
    int p = atomicAdd(&g_cursor[u], 1);
    g_adj[p] = make_float2(__int_as_float(v), w);
    int q = atomicAdd(&g_cursor[v], 1);
    g_adj[q] = make_float2(__int_as_float(u), w);
}

// mark neighbors of batch nodes + the batch nodes themselves
__global__ void mark2_kernel(const int* __restrict__ uids,
                             const int* __restrict__ iids) {
    int idx = (blockIdx.x * blockDim.x + threadIdx.x) >> 5;
    if (idx >= BATCH) return;
    int lane = threadIdx.x & 31;
    int node = (lane < 16) ? uids[idx] : (NU + iids[idx]);
    int sub = lane & 15;
    int start = g_off[node], end = g_off[node + 1];
    for (int p = start + sub; p < end; p += 16) {
        int v = __float_as_int(g_adj[p].x);
        g_flag2[v] = 1;
    }
    if (sub == 0) g_flag2[node] = 1;
}

__global__ void compact2_kernel() {
    int i = blockIdx.x * blockDim.x + threadIdx.x;
    if (i >= NN) return;
    if (g_flag2[i]) { int p = atomicAdd(&g_n2, 1); g_list2[p] = i; }
}

// ---------------- fp16 gather core (8 lanes/node, uint4/lane) ------
__device__ __forceinline__ void acc_row8(const __half* __restrict__ prevH,
                                         int v, int sub, float w, float* acc) {
    uint4 p = ((const uint4*)(prevH + (size_t)v * EMB))[sub];
    float2 f0 = __half22float2(*(__half2*)&p.x);
    float2 f1 = __half22float2(*(__half2*)&p.y);
    float2 f2 = __half22float2(*(__half2*)&p.z);
    float2 f3 = __half22float2(*(__half2*)&p.w);
    acc[0] += w * f0.x; acc[1] += w * f0.y;
    acc[2] += w * f1.x; acc[3] += w * f1.y;
    acc[4] += w * f2.x; acc[5] += w * f2.y;
    acc[6] += w * f3.x; acc[7] += w * f3.y;
}

__device__ __forceinline__ void gather8(int node, int sub, unsigned mask,
                                        const __half* __restrict__ prevH,
                                        float* acc) {
    int start = g_off[node];
    int end   = g_off[node + 1];
    for (int base = start; base < end; base += 8) {
        int n = min(8, end - base);
        float2 e = make_float2(0.f, 0.f);
        if (sub < n) e = g_adj[base + sub];
        int   dr = __float_as_int(e.x);
        float wr = e.y;
        int j = 0;
        for (; j + 4 <= n; j += 4) {
            int   v0 = __shfl_sync(mask, dr, j + 0, 8);
            int   v1 = __shfl_sync(mask, dr, j + 1, 8);
            int   v2 = __shfl_sync(mask, dr, j + 2, 8);
            int   v3 = __shfl_sync(mask, dr, j + 3, 8);
            float w0 = __shfl_sync(mask, wr, j + 0, 8);
            float w1 = __shfl_sync(mask, wr, j + 1, 8);
            float w2 = __shfl_sync(mask, wr, j + 2, 8);
            float w3 = __shfl_sync(mask, wr, j + 3, 8);
            uint4 p0 = ((const uint4*)(prevH + (size_t)v0 * EMB))[sub];
            uint4 p1 = ((const uint4*)(prevH + (size_t)v1 * EMB))[sub];
            uint4 p2 = ((const uint4*)(prevH + (size_t)v2 * EMB))[sub];
            uint4 p3 = ((const uint4*)(prevH + (size_t)v3 * EMB))[sub];
            {
                float2 f0 = __half22float2(*(__half2*)&p0.x);
                float2 f1 = __half22float2(*(__half2*)&p0.y);
                float2 f2 = __half22float2(*(__half2*)&p0.z);
                float2 f3 = __half22float2(*(__half2*)&p0.w);
                acc[0] += w0 * f0.x; acc[1] += w0 * f0.y;
                acc[2] += w0 * f1.x; acc[3] += w0 * f1.y;
                acc[4] += w0 * f2.x; acc[5] += w0 * f2.y;
                acc[6] += w0 * f3.x; acc[7] += w0 * f3.y;
            }
            {
                float2 f0 = __half22float2(*(__half2*)&p1.x);
                float2 f1 = __half22float2(*(__half2*)&p1.y);
                float2 f2 = __half22float2(*(__half2*)&p1.z);
                float2 f3 = __half22float2(*(__half2*)&p1.w);
                acc[0] += w1 * f0.x; acc[1] += w1 * f0.y;
                acc[2] += w1 * f1.x; acc[3] += w1 * f1.y;
                acc[4] += w1 * f2.x; acc[5] += w1 * f2.y;
                acc[6] += w1 * f3.x; acc[7] += w1 * f3.y;
            }
            {
                float2 f0 = __half22float2(*(__half2*)&p2.x);
                float2 f1 = __half22float2(*(__half2*)&p2.y);
                float2 f2 = __half22float2(*(__half2*)&p2.z);
                float2 f3 = __half22float2(*(__half2*)&p2.w);
                acc[0] += w2 * f0.x; acc[1] += w2 * f0.y;
                acc[2] += w2 * f1.x; acc[3] += w2 * f1.y;
                acc[4] += w2 * f2.x; acc[5] += w2 * f2.y;
                acc[6] += w2 * f3.x; acc[7] += w2 * f3.y;
            }
            {
                float2 f0 = __half22float2(*(__half2*)&p3.x);
                float2 f1 = __half22float2(*(__half2*)&p3.y);
                float2 f2 = __half22float2(*(__half2*)&p3.z);
                float2 f3 = __half22float2(*(__half2*)&p3.w);
                acc[0] += w3 * f0.x; acc[1] += w3 * f0.y;
                acc[2] += w3 * f1.x; acc[3] += w3 * f1.y;
                acc[4] += w3 * f2.x; acc[5] += w3 * f2.y;
                acc[6] += w3 * f3.x; acc[7] += w3 * f3.y;
            }
        }
        for (; j < n; j++) {
            int   v = __shfl_sync(mask, dr, j, 8);
            float w = __shfl_sync(mask, wr, j, 8);
            acc_row8(prevH, v, sub, w, acc);
        }
    }
}

__device__ __forceinline__ void store_half8(__half* __restrict__ nextH,
                                            int node, int sub, const float* acc) {
    __half2 o0 = __floats2half2_rn(acc[0], acc[1]);
    __half2 o1 = __floats2half2_rn(acc[2], acc[3]);
    __half2 o2 = __floats2half2_rn(acc[4], acc[5]);
    __half2 o3 = __floats2half2_rn(acc[6], acc[7]);
    uint4 o;
    o.x = *(unsigned*)&o0; o.y = *(unsigned*)&o1;
    o.z = *(unsigned*)&o2; o.w = *(unsigned*)&o3;
    ((uint4*)(nextH + (size_t)node * EMB))[sub] = o;
}

__global__ void prop_full_kernel(const __half* __restrict__ prevH,
                                 __half* __restrict__ nextH) {
    int warpId = (blockIdx.x * blockDim.x + threadIdx.x) >> 5;
    int lane = threadIdx.x & 31;
    int quad = lane >> 3;
    int sub  = lane & 7;
    int node = warpId * 4 + quad;
    if (node >= NN) return;
    unsigned mask = 0xFFu << (quad * 8);
    float acc[8] = {0.f,0.f,0.f,0.f,0.f,0.f,0.f,0.f};
    gather8(node, sub, mask, prevH, acc);
    store_half8(nextH, node, sub, acc);
}

__global__ void prop_list_kernel(const __half* __restrict__ prevH,
                                 __half* __restrict__ nextH,
                                 const int* __restrict__ list,
                                 const int* __restrict__ count) {
    int warpId = (blockIdx.x * blockDim.x + threadIdx.x) >> 5;
    int lane = threadIdx.x & 31;
    int cnt = __shfl_sync(0xffffffffu, (lane == 0) ? *count : 0, 0);
    int quad = lane >> 3;
    int sub  = lane & 7;
    int idx = warpId * 4 + quad;
    if (idx >= cnt) return;
    int node = list[idx];
    unsigned mask = 0xFFu << (quad * 8);
    float acc[8] = {0.f,0.f,0.f,0.f,0.f,0.f,0.f,0.f};
    gather8(node, sub, mask, prevH, acc);
    store_half8(nextH, node, sub, acc);
}

// --------------- fused layer-3 + score -----------------------------
__global__ void score_kernel(const int* __restrict__ uids,
                             const int* __restrict__ iids,
                             const float* __restrict__ ue,
                             const float* __restrict__ ie,
                             float* __restrict__ out) {
    int gt = blockIdx.x * blockDim.x + threadIdx.x;
    int grpG = gt >> 3;
    int sub  = gt & 7;
    int pair = grpG >> 1;
    int side = grpG & 1;
    if (pair >= BATCH) return;
    int lane = threadIdx.x & 31;
    int grp = lane >> 3;
    unsigned gmask = 0xFFu << (grp * 8);

    int node;
    const float4* r0;
    if (side == 0) {
        int u = uids[pair];
        node = u;
        r0 = (const float4*)(ue + (size_t)u * EMB);
    } else {
        int v = iids[pair];
        node = NU + v;
        r0 = (const float4*)(ie + (size_t)v * EMB);
    }

    float w0 = g_w[0], w1 = g_w[1], w2 = g_w[2], w3 = g_w[3];

    float a3[8] = {0.f,0.f,0.f,0.f,0.f,0.f,0.f,0.f};
    gather8(node, sub, gmask, g_h2, a3);

    float4 pa = r0[sub * 2];
    float4 pb = r0[sub * 2 + 1];
    uint4 x1 = ((const uint4*)(g_h1 + (size_t)node * EMB))[sub];
    uint4 x2 = ((const uint4*)(g_h2 + (size_t)node * EMB))[sub];
    float2 l1a = __half22float2(*(__half2*)&x1.x);
    float2 l1b = __half22float2(*(__half2*)&x1.y);
    float2 l1c = __half22float2(*(__half2*)&x1.z);
    float2 l1d = __half22float2(*(__half2*)&x1.w);
    float2 l2a = __half22float2(*(__half2*)&x2.x);
    float2 l2b = __half22float2(*(__half2*)&x2.y);
    float2 l2c = __half22float2(*(__half2*)&x2.z);
    float2 l2d = __half22float2(*(__half2*)&x2.w);

    float f[8];
    f[0] = w0 * pa.x + w1 * l1a.x + w2 * l2a.x + w3 * a3[0];
    f[1] = w0 * pa.y + w1 * l1a.y + w2 * l2a.y + w3 * a3[1];
    f[2] = w0 * pa.z + w1 * l1b.x + w2 * l2b.x + w3 * a3[2];
    f[3] = w0 * pa.w + w1 * l1b.y + w2 * l2b.y + w3 * a3[3];
    f[4] = w0 * pb.x + w1 * l1c.x + w2 * l2c.x + w3 * a3[4];
    f[5] = w0 * pb.y + w1 * l1c.y + w2 * l2c.y + w3 * a3[5];
    f[6] = w0 * pb.z + w1 * l1d.x + w2 * l2d.x + w3 * a3[6];
    f[7] = w0 * pb.w + w1 * l1d.y + w2 * l2d.y + w3 * a3[7];

    float dp = 0.f;
    #pragma unroll
    for (int k = 0; k < 8; k++) {
        float other = __shfl_xor_sync(0xffffffffu, f[k], 8);
        dp += f[k] * other;
    }
    dp += __shfl_down_sync(0xffffffffu, dp, 4, 8);
    dp += __shfl_down_sync(0xffffffffu, dp, 2, 8);
    dp += __shfl_down_sync(0xffffffffu, dp, 1, 8);
    if (side == 0 && sub == 0) out[pair] = dp;
}

// ------------------------- launcher --------------------------------
extern "C" void kernel_launch(void* const* d_in, const int* in_sizes, int n_in,
                              void* d_out, int out_size) {
    const float* user_emb = (const float*)d_in[0];
    const float* item_emb = (const float*)d_in[1];
    const float* layer_w  = (const float*)d_in[2];
    const int*   eu       = (const int*)d_in[3];
    const int*   ei       = (const int*)d_in[4];
    const int*   uids     = (const int*)d_in[5];
    const int*   iids     = (const int*)d_in[6];
    float*       out      = (float*)d_out;
    (void)in_sizes; (void)n_in; (void)out_size;

    __half *h0, *h1, *h2;
    int *list2, *n2;
    cudaGetSymbolAddress((void**)&h0, g_h0);
    cudaGetSymbolAddress((void**)&h1, g_h1);
    cudaGetSymbolAddress((void**)&h2, g_h2);
    cudaGetSymbolAddress((void**)&list2, g_list2);
    cudaGetSymbolAddress((void**)&n2, g_n2);

    cudaStream_t s1;
    cudaStreamCreateWithFlags(&s1, cudaStreamNonBlocking);
    cudaEvent_t evFork, evConv, evFill, evMark;
    cudaEventCreateWithFlags(&evFork, cudaEventDisableTiming);
    cudaEventCreateWithFlags(&evConv, cudaEventDisableTiming);
    cudaEventCreateWithFlags(&evFill, cudaEventDisableTiming);
    cudaEventCreateWithFlags(&evMark, cudaEventDisableTiming);

    // ---- head of critical path: zero counters + softmax ----
    zero_kernel<<<(NN + 255) / 256, 256>>>(layer_w);

    // ---- fork side stream: fp16 conversion (independent) ----
    cudaEventRecord(evFork, 0);
    cudaStreamWaitEvent(s1, evFork, 0);
    const size_t CONV_T = (size_t)NN * EMB / 8;
    conv_kernel<<<(int)((CONV_T + 255) / 256), 256, 0, s1>>>(user_emb, item_emb);
    cudaEventRecord(evConv, s1);

    // ---- CSR chain on main stream ----
    hist_kernel<<<(NE / 4 + 255) / 256, 256>>>(eu, ei);
    scanA_kernel<<<NSB, SCAN_BS>>>();
    scanC_kernel<<<NSB, SCAN_BS>>>();
    fill_kernel<<<(NE + 255) / 256, 256>>>(eu, ei);
    cudaEventRecord(evFill, 0);

    // ---- frontier branch on side stream (overlaps prop_full) ----
    cudaStreamWaitEvent(s1, evFill, 0);
    mark2_kernel<<<(BATCH * 32 + 255) / 256, 256, 0, s1>>>(uids, iids);
    compact2_kernel<<<(NN + 255) / 256, 256, 0, s1>>>();
    cudaEventRecord(evMark, s1);

    // ---- propagation ----
    cudaStreamWaitEvent(0, evConv, 0);
    const int FULL_BLOCKS = ((NN + 3) / 4 * 32 + 255) / 256;
    prop_full_kernel<<<FULL_BLOCKS, 256>>>(h0, h1);
    cudaStreamWaitEvent(0, evMark, 0);
    prop_list_kernel<<<FULL_BLOCKS, 256>>>(h1, h2, list2, n2);

    // ---- fused layer-3 + scores ----
    score_kernel<<<(BATCH * 16 + 255) / 256, 256>>>(uids, iids, user_emb, item_emb, out);

    cudaEventDestroy(evFork);
    cudaEventDestroy(evConv);
    cudaEventDestroy(evFill);
    cudaEventDestroy(evMark);
    cudaStreamDestroy(s1);
}